// round 9
// baseline (speedup 1.0000x reference)
#include <cuda_runtime.h>
#include <cuda_bf16.h>
#include <cuda_fp16.h>
#include <cstdint>
#include <math.h>

// Problem constants
#define B_   2
#define S_   2048
#define HID_ 2048
#define NH_  32
#define NKV_ 8
#define HD_  64
#define GROUP_ 4
#define M_TOT (B_ * S_)          // 4096
#define NKVD (NKV_ * HD_)        // 512
#define NQKV (HID_ + 2 * NKVD)   // 3072

// ---------------------------------------------------------------------------
// Scratch (__device__ globals; no cudaMalloc allowed)
// ---------------------------------------------------------------------------
__device__ float g_QKV[(size_t)M_TOT * NQKV];     // fused projection output

__device__ __nv_bfloat16 g_hh[(size_t)M_TOT * HID_], g_hl[(size_t)M_TOT * HID_];
__device__ __nv_bfloat16 g_wch[(size_t)NQKV * HID_], g_wcl[(size_t)NQKV * HID_];  // wq|wk|wv
__device__ __nv_bfloat16 g_woh[(size_t)HID_ * HID_], g_wol[(size_t)HID_ * HID_];
__device__ __half g_q16[(size_t)M_TOT * HID_];
__device__ __half g_k16[(size_t)M_TOT * NKVD];
__device__ __half g_v16h[(size_t)M_TOT * NKVD], g_v16l[(size_t)M_TOT * NKVD];
__device__ __nv_bfloat16 g_ch[(size_t)M_TOT * HID_], g_cl[(size_t)M_TOT * HID_];

__device__ float g_rsin[S_ * 32], g_rcos[S_ * 32];

// ---------------------------------------------------------------------------
// Helpers
// ---------------------------------------------------------------------------
__device__ __forceinline__ uint32_t smem_u32(const void* p) {
    uint32_t a;
    asm("{ .reg .u64 t; cvta.to.shared.u64 t, %1; cvt.u32.u64 %0, t; }" : "=r"(a) : "l"(p));
    return a;
}
__device__ __forceinline__ void cp16(uint32_t dst, const void* src) {
    asm volatile("cp.async.cg.shared.global [%0], [%1], 16;" :: "r"(dst), "l"(src));
}
__device__ __forceinline__ void cp_commit() { asm volatile("cp.async.commit_group;"); }
__device__ __forceinline__ void cp_wait1() { asm volatile("cp.async.wait_group 1;"); }
__device__ __forceinline__ void cp_wait0() { asm volatile("cp.async.wait_group 0;"); }
__device__ __forceinline__ void ldsm4(uint32_t* r, uint32_t addr) {
    asm volatile("ldmatrix.sync.aligned.m8n8.x4.shared.b16 {%0,%1,%2,%3}, [%4];"
        : "=r"(r[0]), "=r"(r[1]), "=r"(r[2]), "=r"(r[3]) : "r"(addr));
}
__device__ __forceinline__ void ldsm4t(uint32_t* r, uint32_t addr) {
    asm volatile("ldmatrix.sync.aligned.m8n8.x4.trans.shared.b16 {%0,%1,%2,%3}, [%4];"
        : "=r"(r[0]), "=r"(r[1]), "=r"(r[2]), "=r"(r[3]) : "r"(addr));
}
__device__ __forceinline__ void mma_bf16(float* c, const uint32_t* a, const uint32_t* b) {
    asm volatile(
        "mma.sync.aligned.m16n8k16.row.col.f32.bf16.bf16.f32 "
        "{%0,%1,%2,%3}, {%4,%5,%6,%7}, {%8,%9}, {%0,%1,%2,%3};"
        : "+f"(c[0]), "+f"(c[1]), "+f"(c[2]), "+f"(c[3])
        : "r"(a[0]), "r"(a[1]), "r"(a[2]), "r"(a[3]), "r"(b[0]), "r"(b[1]));
}
__device__ __forceinline__ void mma_f16(float* c, const uint32_t* a, const uint32_t* b) {
    asm volatile(
        "mma.sync.aligned.m16n8k16.row.col.f32.f16.f16.f32 "
        "{%0,%1,%2,%3}, {%4,%5,%6,%7}, {%8,%9}, {%0,%1,%2,%3};"
        : "+f"(c[0]), "+f"(c[1]), "+f"(c[2]), "+f"(c[3])
        : "r"(a[0]), "r"(a[1]), "r"(a[2]), "r"(a[3]), "r"(b[0]), "r"(b[1]));
}
__device__ __forceinline__ uint32_t pack_bf16(float x, float y) {
    __nv_bfloat162 h = __floats2bfloat162_rn(x, y);
    return *(uint32_t*)&h;
}
__device__ __forceinline__ uint32_t pack_f16(float x, float y) {
    __half2 h = __floats2half2_rn(x, y);
    return *(uint32_t*)&h;
}

// ---------------------------------------------------------------------------
// fp32 -> bf16 hi/lo split
// ---------------------------------------------------------------------------
__global__ void split_bf16(const float* __restrict__ x,
                           __nv_bfloat16* __restrict__ hi,
                           __nv_bfloat16* __restrict__ lo, int n) {
    int i = blockIdx.x * blockDim.x + threadIdx.x;
    if (i < n) {
        float v = x[i];
        __nv_bfloat16 h = __float2bfloat16(v);
        hi[i] = h;
        lo[i] = __float2bfloat16(v - __bfloat162float(h));
    }
}

// ---------------------------------------------------------------------------
// mma.sync bf16x3 GEMM. CTA tile 128x256x32, 512 thr (16 warps, warp 32x64).
// 3-stage cp.async pipeline, ldmatrix fragments. C[M,N] = A[M,K]*B[N,K]^T.
// (unchanged from the 1340us R6 version)
// ---------------------------------------------------------------------------
#define BM 128
#define BN 256
#define BK 32
#define LDSS 40
#define ATILE (BM * LDSS)
#define BTILE (BN * LDSS)
#define STG_EL (2 * ATILE + 2 * BTILE)
#define GSTG 3

__global__ void __launch_bounds__(512, 1) gemm_mma(
    const __nv_bfloat16* __restrict__ Ah, const __nv_bfloat16* __restrict__ Al,
    const __nv_bfloat16* __restrict__ Bh, const __nv_bfloat16* __restrict__ Bl,
    float* __restrict__ C, int M, int N, int K)
{
    extern __shared__ __nv_bfloat16 dyn[];

    const int tid = threadIdx.x;
    const int warp = tid >> 5, lane = tid & 31;
    const int wm = (warp >> 2) * 32;
    const int wn = (warp & 3) * 64;
    const int g = lane >> 2, t = lane & 3;
    const int l8 = lane & 7, half = (lane >> 3) & 1, kq = lane >> 4;
    const int m0 = blockIdx.y * BM, n0 = blockIdx.x * BN;

    const uint32_t sb = smem_u32(dyn);
    const int arow = tid >> 2, aq = tid & 3;

    float acc[2][8][4];
#pragma unroll
    for (int i = 0; i < 2; i++)
#pragma unroll
        for (int j = 0; j < 8; j++)
#pragma unroll
            for (int x = 0; x < 4; x++) acc[i][j][x] = 0.f;

    const int nch = K / BK;

    auto issue = [&](int kc, int st) {
        uint32_t so = sb + (uint32_t)st * STG_EL * 2;
        size_t ga = (size_t)(m0 + arow) * K + kc * BK + aq * 8;
        uint32_t aoff = (arow * LDSS + aq * 8) * 2;
        cp16(so + aoff,             Ah + ga);
        cp16(so + ATILE * 2 + aoff, Al + ga);
#pragma unroll
        for (int i = 0; i < 2; i++) {
            int idx = tid + i * 512;
            int brow = idx >> 2, bq = idx & 3;
            size_t gb = (size_t)(n0 + brow) * K + kc * BK + bq * 8;
            uint32_t boff = (brow * LDSS + bq * 8) * 2;
            cp16(so + 2 * ATILE * 2 + boff,           Bh + gb);
            cp16(so + (2 * ATILE + BTILE) * 2 + boff, Bl + gb);
        }
        cp_commit();
    };

    issue(0, 0);
    if (nch > 1) issue(1, 1);

    for (int kc = 0; kc < nch; kc++) {
        if (kc + 1 < nch) cp_wait1(); else cp_wait0();
        __syncthreads();
        if (kc + 2 < nch) issue(kc + 2, (kc + 2) % GSTG);

        const uint32_t sa = sb + (uint32_t)(kc % GSTG) * STG_EL * 2;
        const uint32_t sAh_ = sa, sAl_ = sa + ATILE * 2;
        const uint32_t sBh_ = sa + 2 * ATILE * 2, sBl_ = sa + (2 * ATILE + BTILE) * 2;

#pragma unroll
        for (int ks = 0; ks < 2; ks++) {
            const int kb = ks * 16 + kq * 8;
            uint32_t afh[2][4], afl[2][4];
#pragma unroll
            for (int mi = 0; mi < 2; mi++) {
                uint32_t ad = ((wm + mi * 16 + l8 + half * 8) * LDSS + kb) * 2;
                ldsm4(afh[mi], sAh_ + ad);
                ldsm4(afl[mi], sAl_ + ad);
            }
#pragma unroll
            for (int p = 0; p < 4; p++) {
                uint32_t bd = ((wn + p * 16 + l8 + half * 8) * LDSS + kb) * 2;
                uint32_t th[4], tl[4];
                ldsm4(th, sBh_ + bd);
                ldsm4(tl, sBl_ + bd);
                uint32_t be0[2] = {th[0], th[2]}, be1[2] = {th[1], th[3]};
                uint32_t bl0[2] = {tl[0], tl[2]}, bl1[2] = {tl[1], tl[3]};
#pragma unroll
                for (int mi = 0; mi < 2; mi++) {
                    mma_bf16(acc[mi][2 * p],     afh[mi], be0);
                    mma_bf16(acc[mi][2 * p],     afh[mi], bl0);
                    mma_bf16(acc[mi][2 * p],     afl[mi], be0);
                    mma_bf16(acc[mi][2 * p + 1], afh[mi], be1);
                    mma_bf16(acc[mi][2 * p + 1], afh[mi], bl1);
                    mma_bf16(acc[mi][2 * p + 1], afl[mi], be1);
                }
            }
        }
    }

#pragma unroll
    for (int mi = 0; mi < 2; mi++) {
        int r = m0 + wm + mi * 16 + g;
#pragma unroll
        for (int ni = 0; ni < 8; ni++) {
            int c = n0 + wn + ni * 8 + 2 * t;
            *(float2*)&C[(size_t)r * N + c] = make_float2(acc[mi][ni][0], acc[mi][ni][1]);
            *(float2*)&C[(size_t)(r + 8) * N + c] = make_float2(acc[mi][ni][2], acc[mi][ni][3]);
        }
    }
}

// ---------------------------------------------------------------------------
// RoPE: table + apply (fp32 strided in, fp16 packed out)
// ---------------------------------------------------------------------------
__global__ void rope_table_kernel() {
    int i = blockIdx.x * blockDim.x + threadIdx.x;
    int s = i >> 5, f = i & 31;
    double inv_freq = exp(-(double)f / 32.0 * log(10000.0));
    double sd, cd;
    sincos((double)s * inv_freq, &sd, &cd);
    g_rsin[i] = (float)sd;
    g_rcos[i] = (float)cd;
}
__global__ void rope_f16_kernel(const float* __restrict__ X,
                                __half* __restrict__ X16,
                                int nheads, int src_off) {
    int idx = blockIdx.x * blockDim.x + threadIdx.x;
    int i = idx & 31;
    int bh = idx >> 5;
    int h = bh % nheads;
    int bs = bh / nheads;
    int s = bs & (S_ - 1);
    float c = g_rcos[s * 32 + i], sn = g_rsin[s * 32 + i];
    size_t sbase = (size_t)bs * NQKV + src_off + h * HD_;
    size_t dbase = (size_t)bs * nheads * HD_ + (size_t)h * HD_;
    float x1 = X[sbase + i], x2 = X[sbase + i + 32];
    X16[dbase + i]      = __float2half_rn(x1 * c - x2 * sn);
    X16[dbase + i + 32] = __float2half_rn(x2 * c + x1 * sn);
}
__global__ void split_v16_kernel(const float* __restrict__ X,
                                 __half* __restrict__ hi,
                                 __half* __restrict__ lo) {
    int idx = blockIdx.x * blockDim.x + threadIdx.x;   // M_TOT*NKVD
    int row = idx >> 9, col = idx & 511;
    float v = X[(size_t)row * NQKV + HID_ + NKVD + col];
    __half h = __float2half_rn(v);
    hi[idx] = h;
    lo[idx] = __float2half_rn(v - __half2float(h));
}

// ---------------------------------------------------------------------------
// Flash attention: fp16 single-pass QK^T, fp16 2-pass PV (P x (Vh+Vl)).
// 3 smem buffers (K, Vh, Vl), 3-stage cp.async, 2 CTAs/SM.
// grid=(S/128, NH, B), block=256. Heavy-first causal scheduling.
// ---------------------------------------------------------------------------
#define LDK 72
#define KVT (64 * LDK)            // fp16 elems per buffer (9216 B)
#define FSTG 3

__global__ void __launch_bounds__(256, 2) flash_mma(
    const __half* __restrict__ q16, const __half* __restrict__ k16,
    const __half* __restrict__ v16h, const __half* __restrict__ v16l,
    __nv_bfloat16* __restrict__ ch, __nv_bfloat16* __restrict__ cl)
{
    extern __shared__ __half fdyn[];   // FSTG x 3 x KVT

    const int tid = threadIdx.x;
    const int w = tid >> 5, lane = tid & 31;
    const int g = lane >> 2, t = lane & 3;
    const int l8 = lane & 7, half_ = (lane >> 3) & 1, kq = lane >> 4;
    const int qt = (gridDim.x - 1) - blockIdx.x;      // heavy CTAs first
    const int h = blockIdx.y, b = blockIdx.z;
    const int kvh = h / GROUP_;
    const int row_base = qt * 128 + w * 16;
    const float SCALE = 0.125f;
    const uint32_t sb = smem_u32(fdyn);

    // Q fragments (fp16, single precision level)
    uint32_t aq[4][4];
    {
        const __half* qb = q16 + ((size_t)(b * S_ + row_base)) * HID_ + h * HD_;
#pragma unroll
        for (int j = 0; j < 4; j++) {
            int k0 = j * 16 + 2 * t;
            aq[j][0] = *(const uint32_t*)&qb[(size_t)g * HID_ + k0];
            aq[j][1] = *(const uint32_t*)&qb[(size_t)(g + 8) * HID_ + k0];
            aq[j][2] = *(const uint32_t*)&qb[(size_t)g * HID_ + k0 + 8];
            aq[j][3] = *(const uint32_t*)&qb[(size_t)(g + 8) * HID_ + k0 + 8];
        }
    }

    float o[8][4];
#pragma unroll
    for (int i = 0; i < 8; i++)
#pragma unroll
        for (int j = 0; j < 4; j++) o[i][j] = 0.f;
    float m0 = -INFINITY, m1 = -INFINITY, l0 = 0.f, l1 = 0.f;

    const int ntiles = 2 * qt + 2;

    auto issue = [&](int kt, int st) {
        uint32_t so = sb + (uint32_t)st * 3 * KVT * 2;
#pragma unroll
        for (int i = 0; i < 2; i++) {
            int idx = tid + i * 256;
            int r = idx >> 3, q = idx & 7;
            size_t go = ((size_t)(b * S_ + kt * 64 + r)) * NKVD + kvh * HD_ + q * 8;
            uint32_t off = (r * LDK + q * 8) * 2;
            cp16(so + off,               k16 + go);
            cp16(so + KVT * 2 + off,     v16h + go);
            cp16(so + 2 * KVT * 2 + off, v16l + go);
        }
        cp_commit();
    };

    issue(0, 0);
    if (ntiles > 1) issue(1, 1);

    for (int kt = 0; kt < ntiles; kt++) {
        if (kt + 1 < ntiles) cp_wait1(); else cp_wait0();
        __syncthreads();
        if (kt + 2 < ntiles) issue(kt + 2, (kt + 2) % FSTG);

        const uint32_t sg = sb + (uint32_t)(kt % FSTG) * 3 * KVT * 2;
        const uint32_t sK_ = sg;
        const uint32_t sVh_ = sg + KVT * 2, sVl_ = sg + 2 * KVT * 2;

        const bool skip = (kt * 64) > (row_base + 15);
        if (!skip) {
            // --- S = scale * Q K^T (fp16 single pass) ---
            float s[8][4];
#pragma unroll
            for (int i = 0; i < 8; i++)
#pragma unroll
                for (int j = 0; j < 4; j++) s[i][j] = 0.f;
#pragma unroll
            for (int j = 0; j < 4; j++) {
                const int kb = j * 16 + kq * 8;
#pragma unroll
                for (int kp = 0; kp < 4; kp++) {
                    uint32_t ad = ((kp * 16 + l8 + half_ * 8) * LDK + kb) * 2;
                    uint32_t th[4];
                    ldsm4(th, sK_ + ad);
                    uint32_t be0[2] = {th[0], th[2]}, be1[2] = {th[1], th[3]};
                    mma_f16(s[2 * kp],     aq[j], be0);
                    mma_f16(s[2 * kp + 1], aq[j], be1);
                }
            }
            const int r0 = row_base + g, r1 = row_base + g + 8;
#pragma unroll
            for (int ni = 0; ni < 8; ni++) {
                int c0 = kt * 64 + ni * 8 + 2 * t;
                s[ni][0] *= SCALE; s[ni][1] *= SCALE; s[ni][2] *= SCALE; s[ni][3] *= SCALE;
                if ((kt * 64 + 63) > r0 || (kt * 64 + 63) > r1) {
                    if (c0 > r0)     s[ni][0] = -INFINITY;
                    if (c0 + 1 > r0) s[ni][1] = -INFINITY;
                    if (c0 > r1)     s[ni][2] = -INFINITY;
                    if (c0 + 1 > r1) s[ni][3] = -INFINITY;
                }
            }
            // --- softmax update ---
            float mx0 = -INFINITY, mx1 = -INFINITY;
#pragma unroll
            for (int ni = 0; ni < 8; ni++) {
                mx0 = fmaxf(mx0, fmaxf(s[ni][0], s[ni][1]));
                mx1 = fmaxf(mx1, fmaxf(s[ni][2], s[ni][3]));
            }
            mx0 = fmaxf(mx0, __shfl_xor_sync(0xffffffff, mx0, 1));
            mx0 = fmaxf(mx0, __shfl_xor_sync(0xffffffff, mx0, 2));
            mx1 = fmaxf(mx1, __shfl_xor_sync(0xffffffff, mx1, 1));
            mx1 = fmaxf(mx1, __shfl_xor_sync(0xffffffff, mx1, 2));

            float mn0 = fmaxf(m0, mx0), mn1 = fmaxf(m1, mx1);
            float f0 = __expf(m0 - mn0), f1 = __expf(m1 - mn1);
            m0 = mn0; m1 = mn1;

            float sum0 = 0.f, sum1 = 0.f;
#pragma unroll
            for (int ni = 0; ni < 8; ni++) {
                s[ni][0] = __expf(s[ni][0] - mn0);
                s[ni][1] = __expf(s[ni][1] - mn0);
                s[ni][2] = __expf(s[ni][2] - mn1);
                s[ni][3] = __expf(s[ni][3] - mn1);
                sum0 += s[ni][0] + s[ni][1];
                sum1 += s[ni][2] + s[ni][3];
            }
            sum0 += __shfl_xor_sync(0xffffffff, sum0, 1);
            sum0 += __shfl_xor_sync(0xffffffff, sum0, 2);
            sum1 += __shfl_xor_sync(0xffffffff, sum1, 1);
            sum1 += __shfl_xor_sync(0xffffffff, sum1, 2);
            l0 = l0 * f0 + sum0;
            l1 = l1 * f1 + sum1;

#pragma unroll
            for (int nd = 0; nd < 8; nd++) {
                o[nd][0] *= f0; o[nd][1] *= f0;
                o[nd][2] *= f1; o[nd][3] *= f1;
            }

            // --- repack P into fp16 A fragments ---
            uint32_t pf[4][4];
#pragma unroll
            for (int j = 0; j < 4; j++) {
                pf[j][0] = pack_f16(s[2 * j][0],     s[2 * j][1]);
                pf[j][1] = pack_f16(s[2 * j][2],     s[2 * j][3]);
                pf[j][2] = pack_f16(s[2 * j + 1][0], s[2 * j + 1][1]);
                pf[j][3] = pack_f16(s[2 * j + 1][2], s[2 * j + 1][3]);
            }

            // --- O += P (Vh + Vl) : fp16 2-pass ---
#pragma unroll
            for (int j = 0; j < 4; j++) {
#pragma unroll
                for (int dp = 0; dp < 4; dp++) {
                    uint32_t ad = ((j * 16 + kq * 8 + l8) * LDK + dp * 16 + half_ * 8) * 2;
                    uint32_t th[4], tl[4];
                    ldsm4t(th, sVh_ + ad);
                    ldsm4t(tl, sVl_ + ad);
                    uint32_t b0a[2] = {th[0], th[2]}, b1a[2] = {th[1], th[3]};
                    uint32_t b0b[2] = {tl[0], tl[2]}, b1b[2] = {tl[1], tl[3]};
                    mma_f16(o[2 * dp],     pf[j], b0a);
                    mma_f16(o[2 * dp],     pf[j], b0b);
                    mma_f16(o[2 * dp + 1], pf[j], b1a);
                    mma_f16(o[2 * dp + 1], pf[j], b1b);
                }
            }
        }
    }

    // --- normalize and write bf16 hi/lo context ---
    float li0 = 1.0f / l0, li1 = 1.0f / l1;
    const size_t r0 = (size_t)(b * S_ + row_base + g) * HID_ + h * HD_;
    const size_t r1 = (size_t)(b * S_ + row_base + g + 8) * HID_ + h * HD_;
#pragma unroll
    for (int nd = 0; nd < 8; nd++) {
        int c = nd * 8 + 2 * t;
        float v0 = o[nd][0] * li0, v1 = o[nd][1] * li0;
        float v2 = o[nd][2] * li1, v3 = o[nd][3] * li1;
        uint32_t h01 = pack_bf16(v0, v1), h23 = pack_bf16(v2, v3);
        __nv_bfloat162* hp;
        hp = (__nv_bfloat162*)&h01;
        uint32_t l01 = pack_bf16(v0 - __bfloat162float(hp->x), v1 - __bfloat162float(hp->y));
        hp = (__nv_bfloat162*)&h23;
        uint32_t l23 = pack_bf16(v2 - __bfloat162float(hp->x), v3 - __bfloat162float(hp->y));
        *(uint32_t*)&ch[r0 + c] = h01;
        *(uint32_t*)&cl[r0 + c] = l01;
        *(uint32_t*)&ch[r1 + c] = h23;
        *(uint32_t*)&cl[r1 + c] = l23;
    }
}

// ---------------------------------------------------------------------------
// Launch
// ---------------------------------------------------------------------------
extern "C" void kernel_launch(void* const* d_in, const int* in_sizes, int n_in,
                              void* d_out, int out_size)
{
    const float* hidden = (const float*)d_in[0];
    const float* wq = (const float*)d_in[2];
    const float* wk = (const float*)d_in[3];
    const float* wv = (const float*)d_in[4];
    const float* wo = (const float*)d_in[5];
    float* out = (float*)d_out;

    float* qkv;
    cudaGetSymbolAddress((void**)&qkv, g_QKV);

    __nv_bfloat16 *hh, *hl, *wch, *wcl, *woh, *wol, *ch, *cl;
    __half *q16, *k16, *v16h, *v16l;
    cudaGetSymbolAddress((void**)&hh, g_hh);   cudaGetSymbolAddress((void**)&hl, g_hl);
    cudaGetSymbolAddress((void**)&wch, g_wch); cudaGetSymbolAddress((void**)&wcl, g_wcl);
    cudaGetSymbolAddress((void**)&woh, g_woh); cudaGetSymbolAddress((void**)&wol, g_wol);
    cudaGetSymbolAddress((void**)&q16, g_q16); cudaGetSymbolAddress((void**)&k16, g_k16);
    cudaGetSymbolAddress((void**)&v16h, g_v16h); cudaGetSymbolAddress((void**)&v16l, g_v16l);
    cudaGetSymbolAddress((void**)&ch, g_ch);   cudaGetSymbolAddress((void**)&cl, g_cl);

    const int GEMM_DYN = GSTG * STG_EL * 2;      // 184320 B
    const int FLASH_DYN = FSTG * 3 * KVT * 2;    // 82944 B
    cudaFuncSetAttribute(gemm_mma, cudaFuncAttributeMaxDynamicSharedMemorySize, GEMM_DYN);
    cudaFuncSetAttribute(flash_mma, cudaFuncAttributeMaxDynamicSharedMemorySize, FLASH_DYN);

    // Split inputs to bf16 hi/lo (QKV weights concatenated)
    {
        int n1 = M_TOT * HID_;
        split_bf16<<<(n1 + 255) / 256, 256>>>(hidden, hh, hl, n1);
        int n2 = HID_ * HID_;
        split_bf16<<<(n2 + 255) / 256, 256>>>(wq, wch, wcl, n2);
        int n3 = NKVD * HID_;
        split_bf16<<<(n3 + 255) / 256, 256>>>(wk, wch + (size_t)HID_ * HID_, wcl + (size_t)HID_ * HID_, n3);
        split_bf16<<<(n3 + 255) / 256, 256>>>(wv, wch + (size_t)(HID_ + NKVD) * HID_, wcl + (size_t)(HID_ + NKVD) * HID_, n3);
        split_bf16<<<(n2 + 255) / 256, 256>>>(wo, woh, wol, n2);
    }

    rope_table_kernel<<<(S_ * 32) / 256, 256>>>();

    // Fused QKV projection (bf16x3)
    gemm_mma<<<dim3(NQKV / BN, M_TOT / BM), 512, GEMM_DYN>>>(hh, hl, wch, wcl, qkv, M_TOT, NQKV, HID_);

    // RoPE -> fp16 Q/K; V -> fp16 hi/lo
    rope_f16_kernel<<<(M_TOT * NH_ * 32) / 256, 256>>>(qkv, q16, NH_, 0);
    rope_f16_kernel<<<(M_TOT * NKV_ * 32) / 256, 256>>>(qkv, k16, NKV_, HID_);
    split_v16_kernel<<<(M_TOT * NKVD) / 256, 256>>>(qkv, v16h, v16l);

    // Flash attention (fp16 QK single-pass, fp16 PV 2-pass; writes bf16 ctx)
    flash_mma<<<dim3(S_ / 128, NH_, B_), 256, FLASH_DYN>>>(q16, k16, v16h, v16l, ch, cl);

    // O projection (bf16x3)
    gemm_mma<<<dim3(HID_ / BN, M_TOT / BM), 512, GEMM_DYN>>>(ch, cl, woh, wol, out, M_TOT, HID_, HID_);
}

// round 10
// speedup vs baseline: 1.5071x; 1.5071x over previous
#include <cuda_runtime.h>
#include <cuda_bf16.h>
#include <cuda_fp16.h>
#include <cstdint>
#include <math.h>

// Problem constants
#define B_   2
#define S_   2048
#define HID_ 2048
#define NH_  32
#define NKV_ 8
#define HD_  64
#define GROUP_ 4
#define M_TOT (B_ * S_)          // 4096
#define NKVD (NKV_ * HD_)        // 512
#define NQKV (HID_ + 2 * NKVD)   // 3072

// ---------------------------------------------------------------------------
// Scratch (__device__ globals; no cudaMalloc allowed)
// ---------------------------------------------------------------------------
__device__ float g_QKV[(size_t)M_TOT * NQKV];     // fused projection output

__device__ __nv_bfloat16 g_hh[(size_t)M_TOT * HID_], g_hl[(size_t)M_TOT * HID_];
__device__ __nv_bfloat16 g_wch[(size_t)NQKV * HID_], g_wcl[(size_t)NQKV * HID_];  // wq|wk|wv
__device__ __nv_bfloat16 g_woh[(size_t)HID_ * HID_], g_wol[(size_t)HID_ * HID_];
__device__ __half g_q16[(size_t)M_TOT * HID_];
__device__ __half g_k16[(size_t)M_TOT * NKVD];
__device__ __half g_v16h[(size_t)M_TOT * NKVD], g_v16l[(size_t)M_TOT * NKVD];
__device__ __nv_bfloat16 g_ch[(size_t)M_TOT * HID_], g_cl[(size_t)M_TOT * HID_];

__device__ float g_rsin[S_ * 32], g_rcos[S_ * 32];

// ---------------------------------------------------------------------------
// Helpers
// ---------------------------------------------------------------------------
__device__ __forceinline__ uint32_t smem_u32(const void* p) {
    uint32_t a;
    asm("{ .reg .u64 t; cvta.to.shared.u64 t, %1; cvt.u32.u64 %0, t; }" : "=r"(a) : "l"(p));
    return a;
}
__device__ __forceinline__ void cp16(uint32_t dst, const void* src) {
    asm volatile("cp.async.cg.shared.global [%0], [%1], 16;" :: "r"(dst), "l"(src));
}
__device__ __forceinline__ void cp_commit() { asm volatile("cp.async.commit_group;"); }
__device__ __forceinline__ void cp_wait1() { asm volatile("cp.async.wait_group 1;"); }
__device__ __forceinline__ void cp_wait0() { asm volatile("cp.async.wait_group 0;"); }
__device__ __forceinline__ void ldsm4(uint32_t* r, uint32_t addr) {
    asm volatile("ldmatrix.sync.aligned.m8n8.x4.shared.b16 {%0,%1,%2,%3}, [%4];"
        : "=r"(r[0]), "=r"(r[1]), "=r"(r[2]), "=r"(r[3]) : "r"(addr));
}
__device__ __forceinline__ void ldsm4t(uint32_t* r, uint32_t addr) {
    asm volatile("ldmatrix.sync.aligned.m8n8.x4.trans.shared.b16 {%0,%1,%2,%3}, [%4];"
        : "=r"(r[0]), "=r"(r[1]), "=r"(r[2]), "=r"(r[3]) : "r"(addr));
}
__device__ __forceinline__ void mma_bf16(float* c, const uint32_t* a, const uint32_t* b) {
    asm volatile(
        "mma.sync.aligned.m16n8k16.row.col.f32.bf16.bf16.f32 "
        "{%0,%1,%2,%3}, {%4,%5,%6,%7}, {%8,%9}, {%0,%1,%2,%3};"
        : "+f"(c[0]), "+f"(c[1]), "+f"(c[2]), "+f"(c[3])
        : "r"(a[0]), "r"(a[1]), "r"(a[2]), "r"(a[3]), "r"(b[0]), "r"(b[1]));
}
__device__ __forceinline__ void mma_f16(float* c, const uint32_t* a, const uint32_t* b) {
    asm volatile(
        "mma.sync.aligned.m16n8k16.row.col.f32.f16.f16.f32 "
        "{%0,%1,%2,%3}, {%4,%5,%6,%7}, {%8,%9}, {%0,%1,%2,%3};"
        : "+f"(c[0]), "+f"(c[1]), "+f"(c[2]), "+f"(c[3])
        : "r"(a[0]), "r"(a[1]), "r"(a[2]), "r"(a[3]), "r"(b[0]), "r"(b[1]));
}
__device__ __forceinline__ uint32_t pack_bf16(float x, float y) {
    __nv_bfloat162 h = __floats2bfloat162_rn(x, y);
    return *(uint32_t*)&h;
}
__device__ __forceinline__ uint32_t pack_f16(float x, float y) {
    __half2 h = __floats2half2_rn(x, y);
    return *(uint32_t*)&h;
}

// ---------------------------------------------------------------------------
// fp32 -> bf16 hi/lo split
// ---------------------------------------------------------------------------
__global__ void split_bf16(const float* __restrict__ x,
                           __nv_bfloat16* __restrict__ hi,
                           __nv_bfloat16* __restrict__ lo, int n) {
    int i = blockIdx.x * blockDim.x + threadIdx.x;
    if (i < n) {
        float v = x[i];
        __nv_bfloat16 h = __float2bfloat16(v);
        hi[i] = h;
        lo[i] = __float2bfloat16(v - __bfloat162float(h));
    }
}

// ---------------------------------------------------------------------------
// mma.sync bf16x3 GEMM. CTA tile 128x256x32, 512 thr (16 warps, warp 32x64).
// 3-stage cp.async pipeline, ldmatrix fragments. C[M,N] = A[M,K]*B[N,K]^T.
// (identical to the 1340us R6 version)
// ---------------------------------------------------------------------------
#define BM 128
#define BN 256
#define BK 32
#define LDSS 40
#define ATILE (BM * LDSS)
#define BTILE (BN * LDSS)
#define STG_EL (2 * ATILE + 2 * BTILE)
#define GSTG 3

__global__ void __launch_bounds__(512, 1) gemm_mma(
    const __nv_bfloat16* __restrict__ Ah, const __nv_bfloat16* __restrict__ Al,
    const __nv_bfloat16* __restrict__ Bh, const __nv_bfloat16* __restrict__ Bl,
    float* __restrict__ C, int M, int N, int K)
{
    extern __shared__ __nv_bfloat16 dyn[];

    const int tid = threadIdx.x;
    const int warp = tid >> 5, lane = tid & 31;
    const int wm = (warp >> 2) * 32;
    const int wn = (warp & 3) * 64;
    const int g = lane >> 2, t = lane & 3;
    const int l8 = lane & 7, half = (lane >> 3) & 1, kq = lane >> 4;
    const int m0 = blockIdx.y * BM, n0 = blockIdx.x * BN;

    const uint32_t sb = smem_u32(dyn);
    const int arow = tid >> 2, aq = tid & 3;

    float acc[2][8][4];
#pragma unroll
    for (int i = 0; i < 2; i++)
#pragma unroll
        for (int j = 0; j < 8; j++)
#pragma unroll
            for (int x = 0; x < 4; x++) acc[i][j][x] = 0.f;

    const int nch = K / BK;

    auto issue = [&](int kc, int st) {
        uint32_t so = sb + (uint32_t)st * STG_EL * 2;
        size_t ga = (size_t)(m0 + arow) * K + kc * BK + aq * 8;
        uint32_t aoff = (arow * LDSS + aq * 8) * 2;
        cp16(so + aoff,             Ah + ga);
        cp16(so + ATILE * 2 + aoff, Al + ga);
#pragma unroll
        for (int i = 0; i < 2; i++) {
            int idx = tid + i * 512;
            int brow = idx >> 2, bq = idx & 3;
            size_t gb = (size_t)(n0 + brow) * K + kc * BK + bq * 8;
            uint32_t boff = (brow * LDSS + bq * 8) * 2;
            cp16(so + 2 * ATILE * 2 + boff,           Bh + gb);
            cp16(so + (2 * ATILE + BTILE) * 2 + boff, Bl + gb);
        }
        cp_commit();
    };

    issue(0, 0);
    if (nch > 1) issue(1, 1);

    for (int kc = 0; kc < nch; kc++) {
        if (kc + 1 < nch) cp_wait1(); else cp_wait0();
        __syncthreads();
        if (kc + 2 < nch) issue(kc + 2, (kc + 2) % GSTG);

        const uint32_t sa = sb + (uint32_t)(kc % GSTG) * STG_EL * 2;
        const uint32_t sAh_ = sa, sAl_ = sa + ATILE * 2;
        const uint32_t sBh_ = sa + 2 * ATILE * 2, sBl_ = sa + (2 * ATILE + BTILE) * 2;

#pragma unroll
        for (int ks = 0; ks < 2; ks++) {
            const int kb = ks * 16 + kq * 8;
            uint32_t afh[2][4], afl[2][4];
#pragma unroll
            for (int mi = 0; mi < 2; mi++) {
                uint32_t ad = ((wm + mi * 16 + l8 + half * 8) * LDSS + kb) * 2;
                ldsm4(afh[mi], sAh_ + ad);
                ldsm4(afl[mi], sAl_ + ad);
            }
#pragma unroll
            for (int p = 0; p < 4; p++) {
                uint32_t bd = ((wn + p * 16 + l8 + half * 8) * LDSS + kb) * 2;
                uint32_t th[4], tl[4];
                ldsm4(th, sBh_ + bd);
                ldsm4(tl, sBl_ + bd);
                uint32_t be0[2] = {th[0], th[2]}, be1[2] = {th[1], th[3]};
                uint32_t bl0[2] = {tl[0], tl[2]}, bl1[2] = {tl[1], tl[3]};
#pragma unroll
                for (int mi = 0; mi < 2; mi++) {
                    mma_bf16(acc[mi][2 * p],     afh[mi], be0);
                    mma_bf16(acc[mi][2 * p],     afh[mi], bl0);
                    mma_bf16(acc[mi][2 * p],     afl[mi], be0);
                    mma_bf16(acc[mi][2 * p + 1], afh[mi], be1);
                    mma_bf16(acc[mi][2 * p + 1], afh[mi], bl1);
                    mma_bf16(acc[mi][2 * p + 1], afl[mi], be1);
                }
            }
        }
    }

#pragma unroll
    for (int mi = 0; mi < 2; mi++) {
        int r = m0 + wm + mi * 16 + g;
#pragma unroll
        for (int ni = 0; ni < 8; ni++) {
            int c = n0 + wn + ni * 8 + 2 * t;
            *(float2*)&C[(size_t)r * N + c] = make_float2(acc[mi][ni][0], acc[mi][ni][1]);
            *(float2*)&C[(size_t)(r + 8) * N + c] = make_float2(acc[mi][ni][2], acc[mi][ni][3]);
        }
    }
}

// ---------------------------------------------------------------------------
// RoPE: table + apply (fp32 strided in, fp16 packed out)
// ---------------------------------------------------------------------------
__global__ void rope_table_kernel() {
    int i = blockIdx.x * blockDim.x + threadIdx.x;
    int s = i >> 5, f = i & 31;
    double inv_freq = exp(-(double)f / 32.0 * log(10000.0));
    double sd, cd;
    sincos((double)s * inv_freq, &sd, &cd);
    g_rsin[i] = (float)sd;
    g_rcos[i] = (float)cd;
}
__global__ void rope_f16_kernel(const float* __restrict__ X,
                                __half* __restrict__ X16,
                                int nheads, int src_off) {
    int idx = blockIdx.x * blockDim.x + threadIdx.x;
    int i = idx & 31;
    int bh = idx >> 5;
    int h = bh % nheads;
    int bs = bh / nheads;
    int s = bs & (S_ - 1);
    float c = g_rcos[s * 32 + i], sn = g_rsin[s * 32 + i];
    size_t sbase = (size_t)bs * NQKV + src_off + h * HD_;
    size_t dbase = (size_t)bs * nheads * HD_ + (size_t)h * HD_;
    float x1 = X[sbase + i], x2 = X[sbase + i + 32];
    X16[dbase + i]      = __float2half_rn(x1 * c - x2 * sn);
    X16[dbase + i + 32] = __float2half_rn(x2 * c + x1 * sn);
}
__global__ void split_v16_kernel(const float* __restrict__ X,
                                 __half* __restrict__ hi,
                                 __half* __restrict__ lo) {
    int idx = blockIdx.x * blockDim.x + threadIdx.x;   // M_TOT*NKVD
    int row = idx >> 9, col = idx & 511;
    float v = X[(size_t)row * NQKV + HID_ + NKVD + col];
    __half h = __float2half_rn(v);
    hi[idx] = h;
    lo[idx] = __float2half_rn(v - __half2float(h));
}

// ---------------------------------------------------------------------------
// Flash attention: fp16 single-pass QK^T, fp16 2-pass PV (P x (Vh+Vl)).
// 3 smem buffers (K, Vh, Vl), 3-stage cp.async. NO occupancy forcing
// (launch_bounds(256,1)) -- the (256,2) variant spilled registers.
// grid=(S/128, NH, B), block=256. Heavy-first causal scheduling.
// ---------------------------------------------------------------------------
#define LDK 72
#define KVT (64 * LDK)            // fp16 elems per buffer (9216 B)
#define FSTG 3

__global__ void __launch_bounds__(256, 1) flash_mma(
    const __half* __restrict__ q16, const __half* __restrict__ k16,
    const __half* __restrict__ v16h, const __half* __restrict__ v16l,
    __nv_bfloat16* __restrict__ ch, __nv_bfloat16* __restrict__ cl)
{
    extern __shared__ __half fdyn[];   // FSTG x 3 x KVT

    const int tid = threadIdx.x;
    const int w = tid >> 5, lane = tid & 31;
    const int g = lane >> 2, t = lane & 3;
    const int l8 = lane & 7, half_ = (lane >> 3) & 1, kq = lane >> 4;
    const int qt = (gridDim.x - 1) - blockIdx.x;      // heavy CTAs first
    const int h = blockIdx.y, b = blockIdx.z;
    const int kvh = h / GROUP_;
    const int row_base = qt * 128 + w * 16;
    const float SCALE = 0.125f;
    const uint32_t sb = smem_u32(fdyn);

    // Q fragments (fp16, single precision level)
    uint32_t aq[4][4];
    {
        const __half* qb = q16 + ((size_t)(b * S_ + row_base)) * HID_ + h * HD_;
#pragma unroll
        for (int j = 0; j < 4; j++) {
            int k0 = j * 16 + 2 * t;
            aq[j][0] = *(const uint32_t*)&qb[(size_t)g * HID_ + k0];
            aq[j][1] = *(const uint32_t*)&qb[(size_t)(g + 8) * HID_ + k0];
            aq[j][2] = *(const uint32_t*)&qb[(size_t)g * HID_ + k0 + 8];
            aq[j][3] = *(const uint32_t*)&qb[(size_t)(g + 8) * HID_ + k0 + 8];
        }
    }

    float o[8][4];
#pragma unroll
    for (int i = 0; i < 8; i++)
#pragma unroll
        for (int j = 0; j < 4; j++) o[i][j] = 0.f;
    float m0 = -INFINITY, m1 = -INFINITY, l0 = 0.f, l1 = 0.f;

    const int ntiles = 2 * qt + 2;

    auto issue = [&](int kt, int st) {
        uint32_t so = sb + (uint32_t)st * 3 * KVT * 2;
#pragma unroll
        for (int i = 0; i < 2; i++) {
            int idx = tid + i * 256;
            int r = idx >> 3, q = idx & 7;
            size_t go = ((size_t)(b * S_ + kt * 64 + r)) * NKVD + kvh * HD_ + q * 8;
            uint32_t off = (r * LDK + q * 8) * 2;
            cp16(so + off,               k16 + go);
            cp16(so + KVT * 2 + off,     v16h + go);
            cp16(so + 2 * KVT * 2 + off, v16l + go);
        }
        cp_commit();
    };

    issue(0, 0);
    if (ntiles > 1) issue(1, 1);

    for (int kt = 0; kt < ntiles; kt++) {
        if (kt + 1 < ntiles) cp_wait1(); else cp_wait0();
        __syncthreads();
        if (kt + 2 < ntiles) issue(kt + 2, (kt + 2) % FSTG);

        const uint32_t sg = sb + (uint32_t)(kt % FSTG) * 3 * KVT * 2;
        const uint32_t sK_ = sg;
        const uint32_t sVh_ = sg + KVT * 2, sVl_ = sg + 2 * KVT * 2;

        const bool skip = (kt * 64) > (row_base + 15);
        if (!skip) {
            // --- S = scale * Q K^T (fp16 single pass) ---
            float s[8][4];
#pragma unroll
            for (int i = 0; i < 8; i++)
#pragma unroll
                for (int j = 0; j < 4; j++) s[i][j] = 0.f;
#pragma unroll
            for (int j = 0; j < 4; j++) {
                const int kb = j * 16 + kq * 8;
#pragma unroll
                for (int kp = 0; kp < 4; kp++) {
                    uint32_t ad = ((kp * 16 + l8 + half_ * 8) * LDK + kb) * 2;
                    uint32_t th[4];
                    ldsm4(th, sK_ + ad);
                    uint32_t be0[2] = {th[0], th[2]}, be1[2] = {th[1], th[3]};
                    mma_f16(s[2 * kp],     aq[j], be0);
                    mma_f16(s[2 * kp + 1], aq[j], be1);
                }
            }
            const int r0 = row_base + g, r1 = row_base + g + 8;
#pragma unroll
            for (int ni = 0; ni < 8; ni++) {
                int c0 = kt * 64 + ni * 8 + 2 * t;
                s[ni][0] *= SCALE; s[ni][1] *= SCALE; s[ni][2] *= SCALE; s[ni][3] *= SCALE;
                if ((kt * 64 + 63) > r0 || (kt * 64 + 63) > r1) {
                    if (c0 > r0)     s[ni][0] = -INFINITY;
                    if (c0 + 1 > r0) s[ni][1] = -INFINITY;
                    if (c0 > r1)     s[ni][2] = -INFINITY;
                    if (c0 + 1 > r1) s[ni][3] = -INFINITY;
                }
            }
            // --- softmax update ---
            float mx0 = -INFINITY, mx1 = -INFINITY;
#pragma unroll
            for (int ni = 0; ni < 8; ni++) {
                mx0 = fmaxf(mx0, fmaxf(s[ni][0], s[ni][1]));
                mx1 = fmaxf(mx1, fmaxf(s[ni][2], s[ni][3]));
            }
            mx0 = fmaxf(mx0, __shfl_xor_sync(0xffffffff, mx0, 1));
            mx0 = fmaxf(mx0, __shfl_xor_sync(0xffffffff, mx0, 2));
            mx1 = fmaxf(mx1, __shfl_xor_sync(0xffffffff, mx1, 1));
            mx1 = fmaxf(mx1, __shfl_xor_sync(0xffffffff, mx1, 2));

            float mn0 = fmaxf(m0, mx0), mn1 = fmaxf(m1, mx1);
            float f0 = __expf(m0 - mn0), f1 = __expf(m1 - mn1);
            m0 = mn0; m1 = mn1;

            float sum0 = 0.f, sum1 = 0.f;
#pragma unroll
            for (int ni = 0; ni < 8; ni++) {
                s[ni][0] = __expf(s[ni][0] - mn0);
                s[ni][1] = __expf(s[ni][1] - mn0);
                s[ni][2] = __expf(s[ni][2] - mn1);
                s[ni][3] = __expf(s[ni][3] - mn1);
                sum0 += s[ni][0] + s[ni][1];
                sum1 += s[ni][2] + s[ni][3];
            }
            sum0 += __shfl_xor_sync(0xffffffff, sum0, 1);
            sum0 += __shfl_xor_sync(0xffffffff, sum0, 2);
            sum1 += __shfl_xor_sync(0xffffffff, sum1, 1);
            sum1 += __shfl_xor_sync(0xffffffff, sum1, 2);
            l0 = l0 * f0 + sum0;
            l1 = l1 * f1 + sum1;

#pragma unroll
            for (int nd = 0; nd < 8; nd++) {
                o[nd][0] *= f0; o[nd][1] *= f0;
                o[nd][2] *= f1; o[nd][3] *= f1;
            }

            // --- repack P into fp16 A fragments ---
            uint32_t pf[4][4];
#pragma unroll
            for (int j = 0; j < 4; j++) {
                pf[j][0] = pack_f16(s[2 * j][0],     s[2 * j][1]);
                pf[j][1] = pack_f16(s[2 * j][2],     s[2 * j][3]);
                pf[j][2] = pack_f16(s[2 * j + 1][0], s[2 * j + 1][1]);
                pf[j][3] = pack_f16(s[2 * j + 1][2], s[2 * j + 1][3]);
            }

            // --- O += P (Vh + Vl) : fp16 2-pass ---
#pragma unroll
            for (int j = 0; j < 4; j++) {
#pragma unroll
                for (int dp = 0; dp < 4; dp++) {
                    uint32_t ad = ((j * 16 + kq * 8 + l8) * LDK + dp * 16 + half_ * 8) * 2;
                    uint32_t th[4], tl[4];
                    ldsm4t(th, sVh_ + ad);
                    ldsm4t(tl, sVl_ + ad);
                    uint32_t b0a[2] = {th[0], th[2]}, b1a[2] = {th[1], th[3]};
                    uint32_t b0b[2] = {tl[0], tl[2]}, b1b[2] = {tl[1], tl[3]};
                    mma_f16(o[2 * dp],     pf[j], b0a);
                    mma_f16(o[2 * dp],     pf[j], b0b);
                    mma_f16(o[2 * dp + 1], pf[j], b1a);
                    mma_f16(o[2 * dp + 1], pf[j], b1b);
                }
            }
        }
    }

    // --- normalize and write bf16 hi/lo context ---
    float li0 = 1.0f / l0, li1 = 1.0f / l1;
    const size_t r0 = (size_t)(b * S_ + row_base + g) * HID_ + h * HD_;
    const size_t r1 = (size_t)(b * S_ + row_base + g + 8) * HID_ + h * HD_;
#pragma unroll
    for (int nd = 0; nd < 8; nd++) {
        int c = nd * 8 + 2 * t;
        float v0 = o[nd][0] * li0, v1 = o[nd][1] * li0;
        float v2 = o[nd][2] * li1, v3 = o[nd][3] * li1;
        uint32_t h01 = pack_bf16(v0, v1), h23 = pack_bf16(v2, v3);
        __nv_bfloat162* hp;
        hp = (__nv_bfloat162*)&h01;
        uint32_t l01 = pack_bf16(v0 - __bfloat162float(hp->x), v1 - __bfloat162float(hp->y));
        hp = (__nv_bfloat162*)&h23;
        uint32_t l23 = pack_bf16(v2 - __bfloat162float(hp->x), v3 - __bfloat162float(hp->y));
        *(uint32_t*)&ch[r0 + c] = h01;
        *(uint32_t*)&cl[r0 + c] = l01;
        *(uint32_t*)&ch[r1 + c] = h23;
        *(uint32_t*)&cl[r1 + c] = l23;
    }
}

// ---------------------------------------------------------------------------
// Launch
// ---------------------------------------------------------------------------
extern "C" void kernel_launch(void* const* d_in, const int* in_sizes, int n_in,
                              void* d_out, int out_size)
{
    const float* hidden = (const float*)d_in[0];
    const float* wq = (const float*)d_in[2];
    const float* wk = (const float*)d_in[3];
    const float* wv = (const float*)d_in[4];
    const float* wo = (const float*)d_in[5];
    float* out = (float*)d_out;

    float* qkv;
    cudaGetSymbolAddress((void**)&qkv, g_QKV);

    __nv_bfloat16 *hh, *hl, *wch, *wcl, *woh, *wol, *ch, *cl;
    __half *q16, *k16, *v16h, *v16l;
    cudaGetSymbolAddress((void**)&hh, g_hh);   cudaGetSymbolAddress((void**)&hl, g_hl);
    cudaGetSymbolAddress((void**)&wch, g_wch); cudaGetSymbolAddress((void**)&wcl, g_wcl);
    cudaGetSymbolAddress((void**)&woh, g_woh); cudaGetSymbolAddress((void**)&wol, g_wol);
    cudaGetSymbolAddress((void**)&q16, g_q16); cudaGetSymbolAddress((void**)&k16, g_k16);
    cudaGetSymbolAddress((void**)&v16h, g_v16h); cudaGetSymbolAddress((void**)&v16l, g_v16l);
    cudaGetSymbolAddress((void**)&ch, g_ch);   cudaGetSymbolAddress((void**)&cl, g_cl);

    const int GEMM_DYN = GSTG * STG_EL * 2;      // 184320 B
    const int FLASH_DYN = FSTG * 3 * KVT * 2;    // 82944 B
    cudaFuncSetAttribute(gemm_mma, cudaFuncAttributeMaxDynamicSharedMemorySize, GEMM_DYN);
    cudaFuncSetAttribute(flash_mma, cudaFuncAttributeMaxDynamicSharedMemorySize, FLASH_DYN);

    // Split inputs to bf16 hi/lo (QKV weights concatenated)
    {
        int n1 = M_TOT * HID_;
        split_bf16<<<(n1 + 255) / 256, 256>>>(hidden, hh, hl, n1);
        int n2 = HID_ * HID_;
        split_bf16<<<(n2 + 255) / 256, 256>>>(wq, wch, wcl, n2);
        int n3 = NKVD * HID_;
        split_bf16<<<(n3 + 255) / 256, 256>>>(wk, wch + (size_t)HID_ * HID_, wcl + (size_t)HID_ * HID_, n3);
        split_bf16<<<(n3 + 255) / 256, 256>>>(wv, wch + (size_t)(HID_ + NKVD) * HID_, wcl + (size_t)(HID_ + NKVD) * HID_, n3);
        split_bf16<<<(n2 + 255) / 256, 256>>>(wo, woh, wol, n2);
    }

    rope_table_kernel<<<(S_ * 32) / 256, 256>>>();

    // Fused QKV projection (bf16x3)
    gemm_mma<<<dim3(NQKV / BN, M_TOT / BM), 512, GEMM_DYN>>>(hh, hl, wch, wcl, qkv, M_TOT, NQKV, HID_);

    // RoPE -> fp16 Q/K; V -> fp16 hi/lo
    rope_f16_kernel<<<(M_TOT * NH_ * 32) / 256, 256>>>(qkv, q16, NH_, 0);
    rope_f16_kernel<<<(M_TOT * NKV_ * 32) / 256, 256>>>(qkv, k16, NKV_, HID_);
    split_v16_kernel<<<(M_TOT * NKVD) / 256, 256>>>(qkv, v16h, v16l);

    // Flash attention (fp16 QK single-pass, fp16 PV 2-pass; writes bf16 ctx)
    flash_mma<<<dim3(S_ / 128, NH_, B_), 256, FLASH_DYN>>>(q16, k16, v16h, v16l, ch, cl);

    // O projection (bf16x3)
    gemm_mma<<<dim3(HID_ / BN, M_TOT / BM), 512, GEMM_DYN>>>(ch, cl, woh, wol, out, M_TOT, HID_, HID_);
}

// round 11
// speedup vs baseline: 1.8837x; 1.2499x over previous
#include <cuda_runtime.h>
#include <cuda_bf16.h>
#include <cuda_fp16.h>
#include <cstdint>
#include <math.h>

// Problem constants
#define B_   2
#define S_   2048
#define HID_ 2048
#define NH_  32
#define NKV_ 8
#define HD_  64
#define GROUP_ 4
#define M_TOT (B_ * S_)          // 4096
#define NKVD (NKV_ * HD_)        // 512
#define NQKV (HID_ + 2 * NKVD)   // 3072

// ---------------------------------------------------------------------------
// Scratch (__device__ globals; no cudaMalloc allowed)
// ---------------------------------------------------------------------------
__device__ float g_QKV[(size_t)M_TOT * NQKV];     // fused projection output

__device__ __half g_hh[(size_t)M_TOT * HID_], g_hl[(size_t)M_TOT * HID_];  // hidden fp16 hi/lo
__device__ __half g_wc16[(size_t)NQKV * HID_];                             // wq|wk|wv fp16
__device__ __half g_wo16[(size_t)HID_ * HID_];                             // wo fp16
__device__ __half g_q16[(size_t)M_TOT * HID_];
__device__ __half g_k16[(size_t)M_TOT * NKVD];
__device__ __half g_v16h[(size_t)M_TOT * NKVD], g_v16l[(size_t)M_TOT * NKVD];
__device__ __half g_ch[(size_t)M_TOT * HID_], g_cl[(size_t)M_TOT * HID_];  // ctx fp16 hi/lo

__device__ float g_rsin[S_ * 32], g_rcos[S_ * 32];

// ---------------------------------------------------------------------------
// Helpers
// ---------------------------------------------------------------------------
__device__ __forceinline__ uint32_t smem_u32(const void* p) {
    uint32_t a;
    asm("{ .reg .u64 t; cvta.to.shared.u64 t, %1; cvt.u32.u64 %0, t; }" : "=r"(a) : "l"(p));
    return a;
}
__device__ __forceinline__ void cp16(uint32_t dst, const void* src) {
    asm volatile("cp.async.cg.shared.global [%0], [%1], 16;" :: "r"(dst), "l"(src));
}
__device__ __forceinline__ void cp_commit() { asm volatile("cp.async.commit_group;"); }
__device__ __forceinline__ void cp_wait1() { asm volatile("cp.async.wait_group 1;"); }
__device__ __forceinline__ void cp_wait0() { asm volatile("cp.async.wait_group 0;"); }
__device__ __forceinline__ void ldsm4(uint32_t* r, uint32_t addr) {
    asm volatile("ldmatrix.sync.aligned.m8n8.x4.shared.b16 {%0,%1,%2,%3}, [%4];"
        : "=r"(r[0]), "=r"(r[1]), "=r"(r[2]), "=r"(r[3]) : "r"(addr));
}
__device__ __forceinline__ void ldsm4t(uint32_t* r, uint32_t addr) {
    asm volatile("ldmatrix.sync.aligned.m8n8.x4.trans.shared.b16 {%0,%1,%2,%3}, [%4];"
        : "=r"(r[0]), "=r"(r[1]), "=r"(r[2]), "=r"(r[3]) : "r"(addr));
}
__device__ __forceinline__ void mma_f16(float* c, const uint32_t* a, const uint32_t* b) {
    asm volatile(
        "mma.sync.aligned.m16n8k16.row.col.f32.f16.f16.f32 "
        "{%0,%1,%2,%3}, {%4,%5,%6,%7}, {%8,%9}, {%0,%1,%2,%3};"
        : "+f"(c[0]), "+f"(c[1]), "+f"(c[2]), "+f"(c[3])
        : "r"(a[0]), "r"(a[1]), "r"(a[2]), "r"(a[3]), "r"(b[0]), "r"(b[1]));
}
__device__ __forceinline__ uint32_t pack_f16(float x, float y) {
    __half2 h = __floats2half2_rn(x, y);
    return *(uint32_t*)&h;
}

// ---------------------------------------------------------------------------
// Split / convert kernels
// ---------------------------------------------------------------------------
__global__ void split_f16(const float* __restrict__ x,
                          __half* __restrict__ hi, __half* __restrict__ lo, int n) {
    int i = blockIdx.x * blockDim.x + threadIdx.x;
    if (i < n) {
        float v = x[i];
        __half h = __float2half_rn(v);
        hi[i] = h;
        lo[i] = __float2half_rn(v - __half2float(h));
    }
}
__global__ void conv_f16(const float* __restrict__ x, __half* __restrict__ y, int n) {
    int i = blockIdx.x * blockDim.x + threadIdx.x;
    if (i < n) y[i] = __float2half_rn(x[i]);
}

// ---------------------------------------------------------------------------
// fp16 2-pass GEMM: C[M,N] = (Ah+Al)[M,K] * B[N,K]^T, B single fp16.
// CTA 128x256x32, 512 thr (16 warps, warp 32x64), 3-stage cp.async.
// ---------------------------------------------------------------------------
#define BM 128
#define BN 256
#define BK 32
#define LDSS 40
#define ATILE (BM * LDSS)                    // 5120 elems
#define BTILE (BN * LDSS)                    // 10240 elems
#define STG_EL (2 * ATILE + BTILE)           // 20480 elems / stage
#define GSTG 3

__global__ void __launch_bounds__(512, 1) gemm_mma(
    const __half* __restrict__ Ah, const __half* __restrict__ Al,
    const __half* __restrict__ Bm,
    float* __restrict__ C, int M, int N, int K)
{
    extern __shared__ __half dyn[];

    const int tid = threadIdx.x;
    const int warp = tid >> 5, lane = tid & 31;
    const int wm = (warp >> 2) * 32;
    const int wn = (warp & 3) * 64;
    const int g = lane >> 2, t = lane & 3;
    const int l8 = lane & 7, half_ = (lane >> 3) & 1, kq = lane >> 4;
    const int m0 = blockIdx.y * BM, n0 = blockIdx.x * BN;

    const uint32_t sb = smem_u32(dyn);
    const int arow = tid >> 2, aq = tid & 3;

    float acc[2][8][4];
#pragma unroll
    for (int i = 0; i < 2; i++)
#pragma unroll
        for (int j = 0; j < 8; j++)
#pragma unroll
            for (int x = 0; x < 4; x++) acc[i][j][x] = 0.f;

    const int nch = K / BK;

    auto issue = [&](int kc, int st) {
        uint32_t so = sb + (uint32_t)st * STG_EL * 2;
        size_t ga = (size_t)(m0 + arow) * K + kc * BK + aq * 8;
        uint32_t aoff = (arow * LDSS + aq * 8) * 2;
        cp16(so + aoff,             Ah + ga);
        cp16(so + ATILE * 2 + aoff, Al + ga);
#pragma unroll
        for (int i = 0; i < 2; i++) {
            int idx = tid + i * 512;
            int brow = idx >> 2, bq = idx & 3;
            size_t gb = (size_t)(n0 + brow) * K + kc * BK + bq * 8;
            cp16(so + 2 * ATILE * 2 + (brow * LDSS + bq * 8) * 2, Bm + gb);
        }
        cp_commit();
    };

    issue(0, 0);
    if (nch > 1) issue(1, 1);

    for (int kc = 0; kc < nch; kc++) {
        if (kc + 1 < nch) cp_wait1(); else cp_wait0();
        __syncthreads();
        if (kc + 2 < nch) issue(kc + 2, (kc + 2) % GSTG);

        const uint32_t sa = sb + (uint32_t)(kc % GSTG) * STG_EL * 2;
        const uint32_t sAh_ = sa, sAl_ = sa + ATILE * 2;
        const uint32_t sB_ = sa + 2 * ATILE * 2;

#pragma unroll
        for (int ks = 0; ks < 2; ks++) {
            const int kb = ks * 16 + kq * 8;
            uint32_t afh[2][4], afl[2][4];
#pragma unroll
            for (int mi = 0; mi < 2; mi++) {
                uint32_t ad = ((wm + mi * 16 + l8 + half_ * 8) * LDSS + kb) * 2;
                ldsm4(afh[mi], sAh_ + ad);
                ldsm4(afl[mi], sAl_ + ad);
            }
#pragma unroll
            for (int p = 0; p < 4; p++) {
                uint32_t bd = ((wn + p * 16 + l8 + half_ * 8) * LDSS + kb) * 2;
                uint32_t tb[4];
                ldsm4(tb, sB_ + bd);
                uint32_t be0[2] = {tb[0], tb[2]}, be1[2] = {tb[1], tb[3]};
#pragma unroll
                for (int mi = 0; mi < 2; mi++) {
                    mma_f16(acc[mi][2 * p],     afh[mi], be0);
                    mma_f16(acc[mi][2 * p],     afl[mi], be0);
                    mma_f16(acc[mi][2 * p + 1], afh[mi], be1);
                    mma_f16(acc[mi][2 * p + 1], afl[mi], be1);
                }
            }
        }
    }

#pragma unroll
    for (int mi = 0; mi < 2; mi++) {
        int r = m0 + wm + mi * 16 + g;
#pragma unroll
        for (int ni = 0; ni < 8; ni++) {
            int c = n0 + wn + ni * 8 + 2 * t;
            *(float2*)&C[(size_t)r * N + c] = make_float2(acc[mi][ni][0], acc[mi][ni][1]);
            *(float2*)&C[(size_t)(r + 8) * N + c] = make_float2(acc[mi][ni][2], acc[mi][ni][3]);
        }
    }
}

// ---------------------------------------------------------------------------
// RoPE: table + apply (fp32 strided in, fp16 packed out)
// ---------------------------------------------------------------------------
__global__ void rope_table_kernel() {
    int i = blockIdx.x * blockDim.x + threadIdx.x;
    int s = i >> 5, f = i & 31;
    double inv_freq = exp(-(double)f / 32.0 * log(10000.0));
    double sd, cd;
    sincos((double)s * inv_freq, &sd, &cd);
    g_rsin[i] = (float)sd;
    g_rcos[i] = (float)cd;
}
__global__ void rope_f16_kernel(const float* __restrict__ X,
                                __half* __restrict__ X16,
                                int nheads, int src_off) {
    int idx = blockIdx.x * blockDim.x + threadIdx.x;
    int i = idx & 31;
    int bh = idx >> 5;
    int h = bh % nheads;
    int bs = bh / nheads;
    int s = bs & (S_ - 1);
    float c = g_rcos[s * 32 + i], sn = g_rsin[s * 32 + i];
    size_t sbase = (size_t)bs * NQKV + src_off + h * HD_;
    size_t dbase = (size_t)bs * nheads * HD_ + (size_t)h * HD_;
    float x1 = X[sbase + i], x2 = X[sbase + i + 32];
    X16[dbase + i]      = __float2half_rn(x1 * c - x2 * sn);
    X16[dbase + i + 32] = __float2half_rn(x2 * c + x1 * sn);
}
__global__ void split_v16_kernel(const float* __restrict__ X,
                                 __half* __restrict__ hi,
                                 __half* __restrict__ lo) {
    int idx = blockIdx.x * blockDim.x + threadIdx.x;   // M_TOT*NKVD
    int row = idx >> 9, col = idx & 511;
    float v = X[(size_t)row * NQKV + HID_ + NKVD + col];
    __half h = __float2half_rn(v);
    hi[idx] = h;
    lo[idx] = __float2half_rn(v - __half2float(h));
}

// ---------------------------------------------------------------------------
// Flash attention: fp16 single-pass QK^T, fp16 2-pass PV (P x (Vh+Vl)).
// 3 smem buffers, 3-stage cp.async, launch_bounds(256,1) (no spills).
// Epilogue writes fp16 hi/lo context for the 2-pass O-projection.
// ---------------------------------------------------------------------------
#define LDK 72
#define KVT (64 * LDK)
#define FSTG 3

__global__ void __launch_bounds__(256, 1) flash_mma(
    const __half* __restrict__ q16, const __half* __restrict__ k16,
    const __half* __restrict__ v16h, const __half* __restrict__ v16l,
    __half* __restrict__ ch, __half* __restrict__ cl)
{
    extern __shared__ __half fdyn[];   // FSTG x 3 x KVT

    const int tid = threadIdx.x;
    const int w = tid >> 5, lane = tid & 31;
    const int g = lane >> 2, t = lane & 3;
    const int l8 = lane & 7, half_ = (lane >> 3) & 1, kq = lane >> 4;
    const int qt = (gridDim.x - 1) - blockIdx.x;      // heavy CTAs first
    const int h = blockIdx.y, b = blockIdx.z;
    const int kvh = h / GROUP_;
    const int row_base = qt * 128 + w * 16;
    const float SCALE = 0.125f;
    const uint32_t sb = smem_u32(fdyn);

    uint32_t aq[4][4];
    {
        const __half* qb = q16 + ((size_t)(b * S_ + row_base)) * HID_ + h * HD_;
#pragma unroll
        for (int j = 0; j < 4; j++) {
            int k0 = j * 16 + 2 * t;
            aq[j][0] = *(const uint32_t*)&qb[(size_t)g * HID_ + k0];
            aq[j][1] = *(const uint32_t*)&qb[(size_t)(g + 8) * HID_ + k0];
            aq[j][2] = *(const uint32_t*)&qb[(size_t)g * HID_ + k0 + 8];
            aq[j][3] = *(const uint32_t*)&qb[(size_t)(g + 8) * HID_ + k0 + 8];
        }
    }

    float o[8][4];
#pragma unroll
    for (int i = 0; i < 8; i++)
#pragma unroll
        for (int j = 0; j < 4; j++) o[i][j] = 0.f;
    float m0 = -INFINITY, m1 = -INFINITY, l0 = 0.f, l1 = 0.f;

    const int ntiles = 2 * qt + 2;

    auto issue = [&](int kt, int st) {
        uint32_t so = sb + (uint32_t)st * 3 * KVT * 2;
#pragma unroll
        for (int i = 0; i < 2; i++) {
            int idx = tid + i * 256;
            int r = idx >> 3, q = idx & 7;
            size_t go = ((size_t)(b * S_ + kt * 64 + r)) * NKVD + kvh * HD_ + q * 8;
            uint32_t off = (r * LDK + q * 8) * 2;
            cp16(so + off,               k16 + go);
            cp16(so + KVT * 2 + off,     v16h + go);
            cp16(so + 2 * KVT * 2 + off, v16l + go);
        }
        cp_commit();
    };

    issue(0, 0);
    if (ntiles > 1) issue(1, 1);

    for (int kt = 0; kt < ntiles; kt++) {
        if (kt + 1 < ntiles) cp_wait1(); else cp_wait0();
        __syncthreads();
        if (kt + 2 < ntiles) issue(kt + 2, (kt + 2) % FSTG);

        const uint32_t sg = sb + (uint32_t)(kt % FSTG) * 3 * KVT * 2;
        const uint32_t sK_ = sg;
        const uint32_t sVh_ = sg + KVT * 2, sVl_ = sg + 2 * KVT * 2;

        const bool skip = (kt * 64) > (row_base + 15);
        if (!skip) {
            float s[8][4];
#pragma unroll
            for (int i = 0; i < 8; i++)
#pragma unroll
                for (int j = 0; j < 4; j++) s[i][j] = 0.f;
#pragma unroll
            for (int j = 0; j < 4; j++) {
                const int kb = j * 16 + kq * 8;
#pragma unroll
                for (int kp = 0; kp < 4; kp++) {
                    uint32_t ad = ((kp * 16 + l8 + half_ * 8) * LDK + kb) * 2;
                    uint32_t th[4];
                    ldsm4(th, sK_ + ad);
                    uint32_t be0[2] = {th[0], th[2]}, be1[2] = {th[1], th[3]};
                    mma_f16(s[2 * kp],     aq[j], be0);
                    mma_f16(s[2 * kp + 1], aq[j], be1);
                }
            }
            const int r0 = row_base + g, r1 = row_base + g + 8;
#pragma unroll
            for (int ni = 0; ni < 8; ni++) {
                int c0 = kt * 64 + ni * 8 + 2 * t;
                s[ni][0] *= SCALE; s[ni][1] *= SCALE; s[ni][2] *= SCALE; s[ni][3] *= SCALE;
                if ((kt * 64 + 63) > r0 || (kt * 64 + 63) > r1) {
                    if (c0 > r0)     s[ni][0] = -INFINITY;
                    if (c0 + 1 > r0) s[ni][1] = -INFINITY;
                    if (c0 > r1)     s[ni][2] = -INFINITY;
                    if (c0 + 1 > r1) s[ni][3] = -INFINITY;
                }
            }
            float mx0 = -INFINITY, mx1 = -INFINITY;
#pragma unroll
            for (int ni = 0; ni < 8; ni++) {
                mx0 = fmaxf(mx0, fmaxf(s[ni][0], s[ni][1]));
                mx1 = fmaxf(mx1, fmaxf(s[ni][2], s[ni][3]));
            }
            mx0 = fmaxf(mx0, __shfl_xor_sync(0xffffffff, mx0, 1));
            mx0 = fmaxf(mx0, __shfl_xor_sync(0xffffffff, mx0, 2));
            mx1 = fmaxf(mx1, __shfl_xor_sync(0xffffffff, mx1, 1));
            mx1 = fmaxf(mx1, __shfl_xor_sync(0xffffffff, mx1, 2));

            float mn0 = fmaxf(m0, mx0), mn1 = fmaxf(m1, mx1);
            float f0 = __expf(m0 - mn0), f1 = __expf(m1 - mn1);
            m0 = mn0; m1 = mn1;

            float sum0 = 0.f, sum1 = 0.f;
#pragma unroll
            for (int ni = 0; ni < 8; ni++) {
                s[ni][0] = __expf(s[ni][0] - mn0);
                s[ni][1] = __expf(s[ni][1] - mn0);
                s[ni][2] = __expf(s[ni][2] - mn1);
                s[ni][3] = __expf(s[ni][3] - mn1);
                sum0 += s[ni][0] + s[ni][1];
                sum1 += s[ni][2] + s[ni][3];
            }
            sum0 += __shfl_xor_sync(0xffffffff, sum0, 1);
            sum0 += __shfl_xor_sync(0xffffffff, sum0, 2);
            sum1 += __shfl_xor_sync(0xffffffff, sum1, 1);
            sum1 += __shfl_xor_sync(0xffffffff, sum1, 2);
            l0 = l0 * f0 + sum0;
            l1 = l1 * f1 + sum1;

#pragma unroll
            for (int nd = 0; nd < 8; nd++) {
                o[nd][0] *= f0; o[nd][1] *= f0;
                o[nd][2] *= f1; o[nd][3] *= f1;
            }

            uint32_t pf[4][4];
#pragma unroll
            for (int j = 0; j < 4; j++) {
                pf[j][0] = pack_f16(s[2 * j][0],     s[2 * j][1]);
                pf[j][1] = pack_f16(s[2 * j][2],     s[2 * j][3]);
                pf[j][2] = pack_f16(s[2 * j + 1][0], s[2 * j + 1][1]);
                pf[j][3] = pack_f16(s[2 * j + 1][2], s[2 * j + 1][3]);
            }

#pragma unroll
            for (int j = 0; j < 4; j++) {
#pragma unroll
                for (int dp = 0; dp < 4; dp++) {
                    uint32_t ad = ((j * 16 + kq * 8 + l8) * LDK + dp * 16 + half_ * 8) * 2;
                    uint32_t th[4], tl[4];
                    ldsm4t(th, sVh_ + ad);
                    ldsm4t(tl, sVl_ + ad);
                    uint32_t b0a[2] = {th[0], th[2]}, b1a[2] = {th[1], th[3]};
                    uint32_t b0b[2] = {tl[0], tl[2]}, b1b[2] = {tl[1], tl[3]};
                    mma_f16(o[2 * dp],     pf[j], b0a);
                    mma_f16(o[2 * dp],     pf[j], b0b);
                    mma_f16(o[2 * dp + 1], pf[j], b1a);
                    mma_f16(o[2 * dp + 1], pf[j], b1b);
                }
            }
        }
    }

    // --- normalize and write fp16 hi/lo context ---
    float li0 = 1.0f / l0, li1 = 1.0f / l1;
    const size_t r0 = (size_t)(b * S_ + row_base + g) * HID_ + h * HD_;
    const size_t r1 = (size_t)(b * S_ + row_base + g + 8) * HID_ + h * HD_;
#pragma unroll
    for (int nd = 0; nd < 8; nd++) {
        int c = nd * 8 + 2 * t;
        float v0 = o[nd][0] * li0, v1 = o[nd][1] * li0;
        float v2 = o[nd][2] * li1, v3 = o[nd][3] * li1;
        uint32_t h01 = pack_f16(v0, v1), h23 = pack_f16(v2, v3);
        __half2* hp;
        hp = (__half2*)&h01;
        uint32_t l01 = pack_f16(v0 - __half2float(hp->x), v1 - __half2float(hp->y));
        hp = (__half2*)&h23;
        uint32_t l23 = pack_f16(v2 - __half2float(hp->x), v3 - __half2float(hp->y));
        *(uint32_t*)&ch[r0 + c] = h01;
        *(uint32_t*)&cl[r0 + c] = l01;
        *(uint32_t*)&ch[r1 + c] = h23;
        *(uint32_t*)&cl[r1 + c] = l23;
    }
}

// ---------------------------------------------------------------------------
// Launch
// ---------------------------------------------------------------------------
extern "C" void kernel_launch(void* const* d_in, const int* in_sizes, int n_in,
                              void* d_out, int out_size)
{
    const float* hidden = (const float*)d_in[0];
    const float* wq = (const float*)d_in[2];
    const float* wk = (const float*)d_in[3];
    const float* wv = (const float*)d_in[4];
    const float* wo = (const float*)d_in[5];
    float* out = (float*)d_out;

    float* qkv;
    cudaGetSymbolAddress((void**)&qkv, g_QKV);

    __half *hh, *hl, *wc16, *wo16, *q16, *k16, *v16h, *v16l, *ch, *cl;
    cudaGetSymbolAddress((void**)&hh, g_hh);     cudaGetSymbolAddress((void**)&hl, g_hl);
    cudaGetSymbolAddress((void**)&wc16, g_wc16); cudaGetSymbolAddress((void**)&wo16, g_wo16);
    cudaGetSymbolAddress((void**)&q16, g_q16);   cudaGetSymbolAddress((void**)&k16, g_k16);
    cudaGetSymbolAddress((void**)&v16h, g_v16h); cudaGetSymbolAddress((void**)&v16l, g_v16l);
    cudaGetSymbolAddress((void**)&ch, g_ch);     cudaGetSymbolAddress((void**)&cl, g_cl);

    const int GEMM_DYN = GSTG * STG_EL * 2;      // 122880 B
    const int FLASH_DYN = FSTG * 3 * KVT * 2;    // 82944 B
    cudaFuncSetAttribute(gemm_mma, cudaFuncAttributeMaxDynamicSharedMemorySize, GEMM_DYN);
    cudaFuncSetAttribute(flash_mma, cudaFuncAttributeMaxDynamicSharedMemorySize, FLASH_DYN);

    // Splits / converts
    {
        int n1 = M_TOT * HID_;
        split_f16<<<(n1 + 255) / 256, 256>>>(hidden, hh, hl, n1);
        int n2 = HID_ * HID_;
        conv_f16<<<(n2 + 255) / 256, 256>>>(wq, wc16, n2);
        int n3 = NKVD * HID_;
        conv_f16<<<(n3 + 255) / 256, 256>>>(wk, wc16 + (size_t)HID_ * HID_, n3);
        conv_f16<<<(n3 + 255) / 256, 256>>>(wv, wc16 + (size_t)(HID_ + NKVD) * HID_, n3);
        conv_f16<<<(n2 + 255) / 256, 256>>>(wo, wo16, n2);
    }

    rope_table_kernel<<<(S_ * 32) / 256, 256>>>();

    // Fused QKV projection (fp16 2-pass)
    gemm_mma<<<dim3(NQKV / BN, M_TOT / BM), 512, GEMM_DYN>>>(hh, hl, wc16, qkv, M_TOT, NQKV, HID_);

    // RoPE -> fp16 Q/K; V -> fp16 hi/lo
    rope_f16_kernel<<<(M_TOT * NH_ * 32) / 256, 256>>>(qkv, q16, NH_, 0);
    rope_f16_kernel<<<(M_TOT * NKV_ * 32) / 256, 256>>>(qkv, k16, NKV_, HID_);
    split_v16_kernel<<<(M_TOT * NKVD) / 256, 256>>>(qkv, v16h, v16l);

    // Flash attention (fp16; writes fp16 hi/lo ctx)
    flash_mma<<<dim3(S_ / 128, NH_, B_), 256, FLASH_DYN>>>(q16, k16, v16h, v16l, ch, cl);

    // O projection (fp16 2-pass)
    gemm_mma<<<dim3(HID_ / BN, M_TOT / BM), 512, GEMM_DYN>>>(ch, cl, wo16, out, M_TOT, HID_, HID_);
}

// round 13
// speedup vs baseline: 2.6062x; 1.3836x over previous
#include <cuda_runtime.h>
#include <cuda_bf16.h>
#include <cuda_fp16.h>
#include <cstdint>
#include <math.h>

// Problem constants
#define B_   2
#define S_   2048
#define HID_ 2048
#define NH_  32
#define NKV_ 8
#define HD_  64
#define GROUP_ 4
#define M_TOT (B_ * S_)          // 4096
#define NKVD (NKV_ * HD_)        // 512
#define NQKV (HID_ + 2 * NKVD)   // 3072

// ---------------------------------------------------------------------------
// Scratch (__device__ globals; no cudaMalloc allowed)
// ---------------------------------------------------------------------------
__device__ float g_QKV[(size_t)M_TOT * NQKV];     // fused projection output

__device__ __half g_h16[(size_t)M_TOT * HID_];    // hidden fp16
__device__ __half g_wc16[(size_t)NQKV * HID_];    // wq|wk|wv fp16
__device__ __half g_wo16[(size_t)HID_ * HID_];    // wo fp16
__device__ __half g_q16[(size_t)M_TOT * HID_];
__device__ __half g_k16[(size_t)M_TOT * NKVD];
__device__ __half g_v16h[(size_t)M_TOT * NKVD], g_v16l[(size_t)M_TOT * NKVD];
__device__ __half g_c16[(size_t)M_TOT * HID_];    // ctx fp16

__device__ float g_rsin[S_ * 32], g_rcos[S_ * 32];

// ---------------------------------------------------------------------------
// Helpers
// ---------------------------------------------------------------------------
__device__ __forceinline__ uint32_t smem_u32(const void* p) {
    uint32_t a;
    asm("{ .reg .u64 t; cvta.to.shared.u64 t, %1; cvt.u32.u64 %0, t; }" : "=r"(a) : "l"(p));
    return a;
}
__device__ __forceinline__ void cp16(uint32_t dst, const void* src) {
    asm volatile("cp.async.cg.shared.global [%0], [%1], 16;" :: "r"(dst), "l"(src));
}
__device__ __forceinline__ void cp_commit() { asm volatile("cp.async.commit_group;"); }
__device__ __forceinline__ void cp_wait1() { asm volatile("cp.async.wait_group 1;"); }
__device__ __forceinline__ void cp_wait0() { asm volatile("cp.async.wait_group 0;"); }
__device__ __forceinline__ void ldsm4(uint32_t* r, uint32_t addr) {
    asm volatile("ldmatrix.sync.aligned.m8n8.x4.shared.b16 {%0,%1,%2,%3}, [%4];"
        : "=r"(r[0]), "=r"(r[1]), "=r"(r[2]), "=r"(r[3]) : "r"(addr));
}
__device__ __forceinline__ void ldsm4t(uint32_t* r, uint32_t addr) {
    asm volatile("ldmatrix.sync.aligned.m8n8.x4.trans.shared.b16 {%0,%1,%2,%3}, [%4];"
        : "=r"(r[0]), "=r"(r[1]), "=r"(r[2]), "=r"(r[3]) : "r"(addr));
}
__device__ __forceinline__ void mma_f16(float* c, const uint32_t* a, const uint32_t* b) {
    asm volatile(
        "mma.sync.aligned.m16n8k16.row.col.f32.f16.f16.f32 "
        "{%0,%1,%2,%3}, {%4,%5,%6,%7}, {%8,%9}, {%0,%1,%2,%3};"
        : "+f"(c[0]), "+f"(c[1]), "+f"(c[2]), "+f"(c[3])
        : "r"(a[0]), "r"(a[1]), "r"(a[2]), "r"(a[3]), "r"(b[0]), "r"(b[1]));
}
__device__ __forceinline__ uint32_t pack_f16(float x, float y) {
    __half2 h = __floats2half2_rn(x, y);
    return *(uint32_t*)&h;
}

// ---------------------------------------------------------------------------
// Convert / split kernels
// ---------------------------------------------------------------------------
__global__ void conv_f16(const float* __restrict__ x, __half* __restrict__ y, int n) {
    int i = blockIdx.x * blockDim.x + threadIdx.x;
    if (i < n) y[i] = __float2half_rn(x[i]);
}

// ---------------------------------------------------------------------------
// fp16 single-pass GEMM: C[M,N] = A[M,K] * B[N,K]^T.
// CTA 128x256x32, 512 thr (16 warps, warp 32x64), 3-stage cp.async.
// ---------------------------------------------------------------------------
#define BM 128
#define BN 256
#define BK 32
#define LDSS 40
#define ATILE (BM * LDSS)                    // 5120 elems
#define BTILE (BN * LDSS)                    // 10240 elems
#define STG_EL (ATILE + BTILE)               // 15360 elems / stage
#define GSTG 3

__global__ void __launch_bounds__(512, 1) gemm_mma(
    const __half* __restrict__ Am, const __half* __restrict__ Bm,
    float* __restrict__ C, int M, int N, int K)
{
    extern __shared__ __half dyn[];

    const int tid = threadIdx.x;
    const int warp = tid >> 5, lane = tid & 31;
    const int wm = (warp >> 2) * 32;
    const int wn = (warp & 3) * 64;
    const int g = lane >> 2, t = lane & 3;
    const int l8 = lane & 7, half_ = (lane >> 3) & 1, kq = lane >> 4;
    const int m0 = blockIdx.y * BM, n0 = blockIdx.x * BN;

    const uint32_t sb = smem_u32(dyn);
    const int arow = tid >> 2, aq = tid & 3;

    float acc[2][8][4];
#pragma unroll
    for (int i = 0; i < 2; i++)
#pragma unroll
        for (int j = 0; j < 8; j++)
#pragma unroll
            for (int x = 0; x < 4; x++) acc[i][j][x] = 0.f;

    const int nch = K / BK;

    auto issue = [&](int kc, int st) {
        uint32_t so = sb + (uint32_t)st * STG_EL * 2;
        size_t ga = (size_t)(m0 + arow) * K + kc * BK + aq * 8;
        cp16(so + (arow * LDSS + aq * 8) * 2, Am + ga);
#pragma unroll
        for (int i = 0; i < 2; i++) {
            int idx = tid + i * 512;
            int brow = idx >> 2, bq = idx & 3;
            size_t gb = (size_t)(n0 + brow) * K + kc * BK + bq * 8;
            cp16(so + ATILE * 2 + (brow * LDSS + bq * 8) * 2, Bm + gb);
        }
        cp_commit();
    };

    issue(0, 0);
    if (nch > 1) issue(1, 1);

    for (int kc = 0; kc < nch; kc++) {
        if (kc + 1 < nch) cp_wait1(); else cp_wait0();
        __syncthreads();
        if (kc + 2 < nch) issue(kc + 2, (kc + 2) % GSTG);

        const uint32_t sa = sb + (uint32_t)(kc % GSTG) * STG_EL * 2;
        const uint32_t sA_ = sa;
        const uint32_t sB_ = sa + ATILE * 2;

#pragma unroll
        for (int ks = 0; ks < 2; ks++) {
            const int kb = ks * 16 + kq * 8;
            uint32_t af[2][4];
#pragma unroll
            for (int mi = 0; mi < 2; mi++) {
                uint32_t ad = ((wm + mi * 16 + l8 + half_ * 8) * LDSS + kb) * 2;
                ldsm4(af[mi], sA_ + ad);
            }
#pragma unroll
            for (int p = 0; p < 4; p++) {
                uint32_t bd = ((wn + p * 16 + l8 + half_ * 8) * LDSS + kb) * 2;
                uint32_t tb[4];
                ldsm4(tb, sB_ + bd);
                uint32_t be0[2] = {tb[0], tb[2]}, be1[2] = {tb[1], tb[3]};
#pragma unroll
                for (int mi = 0; mi < 2; mi++) {
                    mma_f16(acc[mi][2 * p],     af[mi], be0);
                    mma_f16(acc[mi][2 * p + 1], af[mi], be1);
                }
            }
        }
    }

#pragma unroll
    for (int mi = 0; mi < 2; mi++) {
        int r = m0 + wm + mi * 16 + g;
#pragma unroll
        for (int ni = 0; ni < 8; ni++) {
            int c = n0 + wn + ni * 8 + 2 * t;
            *(float2*)&C[(size_t)r * N + c] = make_float2(acc[mi][ni][0], acc[mi][ni][1]);
            *(float2*)&C[(size_t)(r + 8) * N + c] = make_float2(acc[mi][ni][2], acc[mi][ni][3]);
        }
    }
}

// ---------------------------------------------------------------------------
// RoPE: table + apply (fp32 strided in, fp16 packed out)
// ---------------------------------------------------------------------------
__global__ void rope_table_kernel() {
    int i = blockIdx.x * blockDim.x + threadIdx.x;
    int s = i >> 5, f = i & 31;
    double inv_freq = exp(-(double)f / 32.0 * log(10000.0));
    double sd, cd;
    sincos((double)s * inv_freq, &sd, &cd);
    g_rsin[i] = (float)sd;
    g_rcos[i] = (float)cd;
}
__global__ void rope_f16_kernel(const float* __restrict__ X,
                                __half* __restrict__ X16,
                                int nheads, int src_off) {
    int idx = blockIdx.x * blockDim.x + threadIdx.x;
    int i = idx & 31;
    int bh = idx >> 5;
    int h = bh % nheads;
    int bs = bh / nheads;
    int s = bs & (S_ - 1);
    float c = g_rcos[s * 32 + i], sn = g_rsin[s * 32 + i];
    size_t sbase = (size_t)bs * NQKV + src_off + h * HD_;
    size_t dbase = (size_t)bs * nheads * HD_ + (size_t)h * HD_;
    float x1 = X[sbase + i], x2 = X[sbase + i + 32];
    X16[dbase + i]      = __float2half_rn(x1 * c - x2 * sn);
    X16[dbase + i + 32] = __float2half_rn(x2 * c + x1 * sn);
}
__global__ void split_v16_kernel(const float* __restrict__ X,
                                 __half* __restrict__ hi,
                                 __half* __restrict__ lo) {
    int idx = blockIdx.x * blockDim.x + threadIdx.x;   // M_TOT*NKVD
    int row = idx >> 9, col = idx & 511;
    float v = X[(size_t)row * NQKV + HID_ + NKVD + col];
    __half h = __float2half_rn(v);
    hi[idx] = h;
    lo[idx] = __float2half_rn(v - __half2float(h));
}

// ---------------------------------------------------------------------------
// Flash attention: fp16 single-pass QK^T, fp16 2-pass PV (P x (Vh+Vl)).
// 3 smem buffers, 3-stage cp.async, launch_bounds(256,1).
// Epilogue writes single fp16 context for the 1-pass O-projection.
// ---------------------------------------------------------------------------
#define LDK 72
#define KVT (64 * LDK)
#define FSTG 3

__global__ void __launch_bounds__(256, 1) flash_mma(
    const __half* __restrict__ q16, const __half* __restrict__ k16,
    const __half* __restrict__ v16h, const __half* __restrict__ v16l,
    __half* __restrict__ c16)
{
    extern __shared__ __half fdyn[];   // FSTG x 3 x KVT

    const int tid = threadIdx.x;
    const int w = tid >> 5, lane = tid & 31;
    const int g = lane >> 2, t = lane & 3;
    const int l8 = lane & 7, half_ = (lane >> 3) & 1, kq = lane >> 4;
    const int qt = (gridDim.x - 1) - blockIdx.x;      // heavy CTAs first
    const int h = blockIdx.y, b = blockIdx.z;
    const int kvh = h / GROUP_;
    const int row_base = qt * 128 + w * 16;
    const float SCALE = 0.125f;
    const uint32_t sb = smem_u32(fdyn);

    uint32_t aq[4][4];
    {
        const __half* qb = q16 + ((size_t)(b * S_ + row_base)) * HID_ + h * HD_;
#pragma unroll
        for (int j = 0; j < 4; j++) {
            int k0 = j * 16 + 2 * t;
            aq[j][0] = *(const uint32_t*)&qb[(size_t)g * HID_ + k0];
            aq[j][1] = *(const uint32_t*)&qb[(size_t)(g + 8) * HID_ + k0];
            aq[j][2] = *(const uint32_t*)&qb[(size_t)g * HID_ + k0 + 8];
            aq[j][3] = *(const uint32_t*)&qb[(size_t)(g + 8) * HID_ + k0 + 8];
        }
    }

    float o[8][4];
#pragma unroll
    for (int i = 0; i < 8; i++)
#pragma unroll
        for (int j = 0; j < 4; j++) o[i][j] = 0.f;
    float m0 = -INFINITY, m1 = -INFINITY, l0 = 0.f, l1 = 0.f;

    const int ntiles = 2 * qt + 2;

    auto issue = [&](int kt, int st) {
        uint32_t so = sb + (uint32_t)st * 3 * KVT * 2;
#pragma unroll
        for (int i = 0; i < 2; i++) {
            int idx = tid + i * 256;
            int r = idx >> 3, q = idx & 7;
            size_t go = ((size_t)(b * S_ + kt * 64 + r)) * NKVD + kvh * HD_ + q * 8;
            uint32_t off = (r * LDK + q * 8) * 2;
            cp16(so + off,               k16 + go);
            cp16(so + KVT * 2 + off,     v16h + go);
            cp16(so + 2 * KVT * 2 + off, v16l + go);
        }
        cp_commit();
    };

    issue(0, 0);
    if (ntiles > 1) issue(1, 1);

    for (int kt = 0; kt < ntiles; kt++) {
        if (kt + 1 < ntiles) cp_wait1(); else cp_wait0();
        __syncthreads();
        if (kt + 2 < ntiles) issue(kt + 2, (kt + 2) % FSTG);

        const uint32_t sg = sb + (uint32_t)(kt % FSTG) * 3 * KVT * 2;
        const uint32_t sK_ = sg;
        const uint32_t sVh_ = sg + KVT * 2, sVl_ = sg + 2 * KVT * 2;

        const bool skip = (kt * 64) > (row_base + 15);
        if (!skip) {
            float s[8][4];
#pragma unroll
            for (int i = 0; i < 8; i++)
#pragma unroll
                for (int j = 0; j < 4; j++) s[i][j] = 0.f;
#pragma unroll
            for (int j = 0; j < 4; j++) {
                const int kb = j * 16 + kq * 8;
#pragma unroll
                for (int kp = 0; kp < 4; kp++) {
                    uint32_t ad = ((kp * 16 + l8 + half_ * 8) * LDK + kb) * 2;
                    uint32_t th[4];
                    ldsm4(th, sK_ + ad);
                    uint32_t be0[2] = {th[0], th[2]}, be1[2] = {th[1], th[3]};
                    mma_f16(s[2 * kp],     aq[j], be0);
                    mma_f16(s[2 * kp + 1], aq[j], be1);
                }
            }
            const int r0 = row_base + g, r1 = row_base + g + 8;
#pragma unroll
            for (int ni = 0; ni < 8; ni++) {
                int c0 = kt * 64 + ni * 8 + 2 * t;
                s[ni][0] *= SCALE; s[ni][1] *= SCALE; s[ni][2] *= SCALE; s[ni][3] *= SCALE;
                if ((kt * 64 + 63) > r0 || (kt * 64 + 63) > r1) {
                    if (c0 > r0)     s[ni][0] = -INFINITY;
                    if (c0 + 1 > r0) s[ni][1] = -INFINITY;
                    if (c0 > r1)     s[ni][2] = -INFINITY;
                    if (c0 + 1 > r1) s[ni][3] = -INFINITY;
                }
            }
            float mx0 = -INFINITY, mx1 = -INFINITY;
#pragma unroll
            for (int ni = 0; ni < 8; ni++) {
                mx0 = fmaxf(mx0, fmaxf(s[ni][0], s[ni][1]));
                mx1 = fmaxf(mx1, fmaxf(s[ni][2], s[ni][3]));
            }
            mx0 = fmaxf(mx0, __shfl_xor_sync(0xffffffff, mx0, 1));
            mx0 = fmaxf(mx0, __shfl_xor_sync(0xffffffff, mx0, 2));
            mx1 = fmaxf(mx1, __shfl_xor_sync(0xffffffff, mx1, 1));
            mx1 = fmaxf(mx1, __shfl_xor_sync(0xffffffff, mx1, 2));

            float mn0 = fmaxf(m0, mx0), mn1 = fmaxf(m1, mx1);
            float f0 = __expf(m0 - mn0), f1 = __expf(m1 - mn1);
            m0 = mn0; m1 = mn1;

            float sum0 = 0.f, sum1 = 0.f;
#pragma unroll
            for (int ni = 0; ni < 8; ni++) {
                s[ni][0] = __expf(s[ni][0] - mn0);
                s[ni][1] = __expf(s[ni][1] - mn0);
                s[ni][2] = __expf(s[ni][2] - mn1);
                s[ni][3] = __expf(s[ni][3] - mn1);
                sum0 += s[ni][0] + s[ni][1];
                sum1 += s[ni][2] + s[ni][3];
            }
            sum0 += __shfl_xor_sync(0xffffffff, sum0, 1);
            sum0 += __shfl_xor_sync(0xffffffff, sum0, 2);
            sum1 += __shfl_xor_sync(0xffffffff, sum1, 1);
            sum1 += __shfl_xor_sync(0xffffffff, sum1, 2);
            l0 = l0 * f0 + sum0;
            l1 = l1 * f1 + sum1;

#pragma unroll
            for (int nd = 0; nd < 8; nd++) {
                o[nd][0] *= f0; o[nd][1] *= f0;
                o[nd][2] *= f1; o[nd][3] *= f1;
            }

            uint32_t pf[4][4];
#pragma unroll
            for (int j = 0; j < 4; j++) {
                pf[j][0] = pack_f16(s[2 * j][0],     s[2 * j][1]);
                pf[j][1] = pack_f16(s[2 * j][2],     s[2 * j][3]);
                pf[j][2] = pack_f16(s[2 * j + 1][0], s[2 * j + 1][1]);
                pf[j][3] = pack_f16(s[2 * j + 1][2], s[2 * j + 1][3]);
            }

#pragma unroll
            for (int j = 0; j < 4; j++) {
#pragma unroll
                for (int dp = 0; dp < 4; dp++) {
                    uint32_t ad = ((j * 16 + kq * 8 + l8) * LDK + dp * 16 + half_ * 8) * 2;
                    uint32_t th[4], tl[4];
                    ldsm4t(th, sVh_ + ad);
                    ldsm4t(tl, sVl_ + ad);
                    uint32_t b0a[2] = {th[0], th[2]}, b1a[2] = {th[1], th[3]};
                    uint32_t b0b[2] = {tl[0], tl[2]}, b1b[2] = {tl[1], tl[3]};
                    mma_f16(o[2 * dp],     pf[j], b0a);
                    mma_f16(o[2 * dp],     pf[j], b0b);
                    mma_f16(o[2 * dp + 1], pf[j], b1a);
                    mma_f16(o[2 * dp + 1], pf[j], b1b);
                }
            }
        }
    }

    // --- normalize and write fp16 context ---
    float li0 = 1.0f / l0, li1 = 1.0f / l1;
    const size_t r0 = (size_t)(b * S_ + row_base + g) * HID_ + h * HD_;
    const size_t r1 = (size_t)(b * S_ + row_base + g + 8) * HID_ + h * HD_;
#pragma unroll
    for (int nd = 0; nd < 8; nd++) {
        int c = nd * 8 + 2 * t;
        *(uint32_t*)&c16[r0 + c] = pack_f16(o[nd][0] * li0, o[nd][1] * li0);
        *(uint32_t*)&c16[r1 + c] = pack_f16(o[nd][2] * li1, o[nd][3] * li1);
    }
}

// ---------------------------------------------------------------------------
// Launch
// ---------------------------------------------------------------------------
extern "C" void kernel_launch(void* const* d_in, const int* in_sizes, int n_in,
                              void* d_out, int out_size)
{
    const float* hidden = (const float*)d_in[0];
    const float* wq = (const float*)d_in[2];
    const float* wk = (const float*)d_in[3];
    const float* wv = (const float*)d_in[4];
    const float* wo = (const float*)d_in[5];
    float* out = (float*)d_out;

    float* qkv;
    cudaGetSymbolAddress((void**)&qkv, g_QKV);

    __half *h16, *wc16, *wo16, *q16, *k16, *v16h, *v16l, *c16;
    cudaGetSymbolAddress((void**)&h16, g_h16);
    cudaGetSymbolAddress((void**)&wc16, g_wc16); cudaGetSymbolAddress((void**)&wo16, g_wo16);
    cudaGetSymbolAddress((void**)&q16, g_q16);   cudaGetSymbolAddress((void**)&k16, g_k16);
    cudaGetSymbolAddress((void**)&v16h, g_v16h); cudaGetSymbolAddress((void**)&v16l, g_v16l);
    cudaGetSymbolAddress((void**)&c16, g_c16);

    const int GEMM_DYN = GSTG * STG_EL * 2;      // 92160 B
    const int FLASH_DYN = FSTG * 3 * KVT * 2;    // 82944 B
    cudaFuncSetAttribute(gemm_mma, cudaFuncAttributeMaxDynamicSharedMemorySize, GEMM_DYN);
    cudaFuncSetAttribute(flash_mma, cudaFuncAttributeMaxDynamicSharedMemorySize, FLASH_DYN);

    // Converts
    {
        int n1 = M_TOT * HID_;
        conv_f16<<<(n1 + 255) / 256, 256>>>(hidden, h16, n1);
        int n2 = HID_ * HID_;
        conv_f16<<<(n2 + 255) / 256, 256>>>(wq, wc16, n2);
        int n3 = NKVD * HID_;
        conv_f16<<<(n3 + 255) / 256, 256>>>(wk, wc16 + (size_t)HID_ * HID_, n3);
        conv_f16<<<(n3 + 255) / 256, 256>>>(wv, wc16 + (size_t)(HID_ + NKVD) * HID_, n3);
        conv_f16<<<(n2 + 255) / 256, 256>>>(wo, wo16, n2);
    }

    rope_table_kernel<<<(S_ * 32) / 256, 256>>>();

    // Fused QKV projection (fp16 1-pass)
    gemm_mma<<<dim3(NQKV / BN, M_TOT / BM), 512, GEMM_DYN>>>(h16, wc16, qkv, M_TOT, NQKV, HID_);

    // RoPE -> fp16 Q/K; V -> fp16 hi/lo
    rope_f16_kernel<<<(M_TOT * NH_ * 32) / 256, 256>>>(qkv, q16, NH_, 0);
    rope_f16_kernel<<<(M_TOT * NKV_ * 32) / 256, 256>>>(qkv, k16, NKV_, HID_);
    split_v16_kernel<<<(M_TOT * NKVD) / 256, 256>>>(qkv, v16h, v16l);

    // Flash attention (fp16; writes fp16 ctx)
    flash_mma<<<dim3(S_ / 128, NH_, B_), 256, FLASH_DYN>>>(q16, k16, v16h, v16l, c16);

    // O projection (fp16 1-pass)
    gemm_mma<<<dim3(HID_ / BN, M_TOT / BM), 512, GEMM_DYN>>>(c16, wo16, out, M_TOT, HID_, HID_);
}

// round 14
// speedup vs baseline: 2.8982x; 1.1120x over previous
#include <cuda_runtime.h>
#include <cuda_bf16.h>
#include <cuda_fp16.h>
#include <cstdint>
#include <math.h>

// Problem constants
#define B_   2
#define S_   2048
#define HID_ 2048
#define NH_  32
#define NKV_ 8
#define HD_  64
#define GROUP_ 4
#define M_TOT (B_ * S_)          // 4096
#define NKVD (NKV_ * HD_)        // 512
#define NQKV (HID_ + 2 * NKVD)   // 3072

// ---------------------------------------------------------------------------
// Scratch (__device__ globals; no cudaMalloc allowed)
// ---------------------------------------------------------------------------
__device__ float g_QKV[(size_t)M_TOT * NQKV];     // fused projection output

__device__ __half g_h16[(size_t)M_TOT * HID_];    // hidden fp16
__device__ __half g_wc16[(size_t)NQKV * HID_];    // wq|wk|wv fp16
__device__ __half g_wo16[(size_t)HID_ * HID_];    // wo fp16
__device__ __half g_q16[(size_t)M_TOT * HID_];
__device__ __half g_k16[(size_t)M_TOT * NKVD];
__device__ __half g_v16[(size_t)M_TOT * NKVD];
__device__ __half g_c16[(size_t)M_TOT * HID_];    // ctx fp16

__device__ float g_rsin[S_ * 32], g_rcos[S_ * 32];

// ---------------------------------------------------------------------------
// Helpers
// ---------------------------------------------------------------------------
__device__ __forceinline__ uint32_t smem_u32(const void* p) {
    uint32_t a;
    asm("{ .reg .u64 t; cvta.to.shared.u64 t, %1; cvt.u32.u64 %0, t; }" : "=r"(a) : "l"(p));
    return a;
}
__device__ __forceinline__ void cp16(uint32_t dst, const void* src) {
    asm volatile("cp.async.cg.shared.global [%0], [%1], 16;" :: "r"(dst), "l"(src));
}
__device__ __forceinline__ void cp_commit() { asm volatile("cp.async.commit_group;"); }
__device__ __forceinline__ void cp_wait1() { asm volatile("cp.async.wait_group 1;"); }
__device__ __forceinline__ void cp_wait0() { asm volatile("cp.async.wait_group 0;"); }
__device__ __forceinline__ void ldsm4(uint32_t* r, uint32_t addr) {
    asm volatile("ldmatrix.sync.aligned.m8n8.x4.shared.b16 {%0,%1,%2,%3}, [%4];"
        : "=r"(r[0]), "=r"(r[1]), "=r"(r[2]), "=r"(r[3]) : "r"(addr));
}
__device__ __forceinline__ void ldsm4t(uint32_t* r, uint32_t addr) {
    asm volatile("ldmatrix.sync.aligned.m8n8.x4.trans.shared.b16 {%0,%1,%2,%3}, [%4];"
        : "=r"(r[0]), "=r"(r[1]), "=r"(r[2]), "=r"(r[3]) : "r"(addr));
}
__device__ __forceinline__ void mma_f16(float* c, const uint32_t* a, const uint32_t* b) {
    asm volatile(
        "mma.sync.aligned.m16n8k16.row.col.f32.f16.f16.f32 "
        "{%0,%1,%2,%3}, {%4,%5,%6,%7}, {%8,%9}, {%0,%1,%2,%3};"
        : "+f"(c[0]), "+f"(c[1]), "+f"(c[2]), "+f"(c[3])
        : "r"(a[0]), "r"(a[1]), "r"(a[2]), "r"(a[3]), "r"(b[0]), "r"(b[1]));
}
__device__ __forceinline__ uint32_t pack_f16(float x, float y) {
    __half2 h = __floats2half2_rn(x, y);
    return *(uint32_t*)&h;
}

// ---------------------------------------------------------------------------
// Fused convert: hidden + wq + wk + wv + wo -> fp16, one launch
// ---------------------------------------------------------------------------
#define CN1 (M_TOT * HID_)       // hidden
#define CN2 (HID_ * HID_)        // wq
#define CN3 (NKVD * HID_)        // wk
#define CN4 (NKVD * HID_)        // wv
#define CN5 (HID_ * HID_)        // wo
#define CTOT (CN1 + CN2 + CN3 + CN4 + CN5)

__global__ void conv_all(const float* __restrict__ hidden,
                         const float* __restrict__ wq, const float* __restrict__ wk,
                         const float* __restrict__ wv, const float* __restrict__ wo,
                         __half* __restrict__ h16, __half* __restrict__ wc16,
                         __half* __restrict__ wo16) {
    int i = blockIdx.x * blockDim.x + threadIdx.x;
    if (i < CN1) {
        h16[i] = __float2half_rn(hidden[i]);
    } else if (i < CN1 + CN2) {
        int j = i - CN1;
        wc16[j] = __float2half_rn(wq[j]);
    } else if (i < CN1 + CN2 + CN3) {
        int j = i - (CN1 + CN2);
        wc16[CN2 + j] = __float2half_rn(wk[j]);
    } else if (i < CN1 + CN2 + CN3 + CN4) {
        int j = i - (CN1 + CN2 + CN3);
        wc16[CN2 + CN3 + j] = __float2half_rn(wv[j]);
    } else if (i < CTOT) {
        int j = i - (CN1 + CN2 + CN3 + CN4);
        wo16[j] = __float2half_rn(wo[j]);
    }
}

// ---------------------------------------------------------------------------
// fp16 single-pass GEMM: C[M,N] = A[M,K] * B[N,K]^T.
// CTA 128x256x32, 512 thr (16 warps, warp 32x64), 3-stage cp.async.
// ---------------------------------------------------------------------------
#define BM 128
#define BN 256
#define BK 32
#define LDSS 40
#define ATILE (BM * LDSS)
#define BTILE (BN * LDSS)
#define STG_EL (ATILE + BTILE)
#define GSTG 3

__global__ void __launch_bounds__(512, 1) gemm_mma(
    const __half* __restrict__ Am, const __half* __restrict__ Bm,
    float* __restrict__ C, int M, int N, int K)
{
    extern __shared__ __half dyn[];

    const int tid = threadIdx.x;
    const int warp = tid >> 5, lane = tid & 31;
    const int wm = (warp >> 2) * 32;
    const int wn = (warp & 3) * 64;
    const int g = lane >> 2, t = lane & 3;
    const int l8 = lane & 7, half_ = (lane >> 3) & 1, kq = lane >> 4;
    const int m0 = blockIdx.y * BM, n0 = blockIdx.x * BN;

    const uint32_t sb = smem_u32(dyn);
    const int arow = tid >> 2, aq = tid & 3;

    float acc[2][8][4];
#pragma unroll
    for (int i = 0; i < 2; i++)
#pragma unroll
        for (int j = 0; j < 8; j++)
#pragma unroll
            for (int x = 0; x < 4; x++) acc[i][j][x] = 0.f;

    const int nch = K / BK;

    auto issue = [&](int kc, int st) {
        uint32_t so = sb + (uint32_t)st * STG_EL * 2;
        size_t ga = (size_t)(m0 + arow) * K + kc * BK + aq * 8;
        cp16(so + (arow * LDSS + aq * 8) * 2, Am + ga);
#pragma unroll
        for (int i = 0; i < 2; i++) {
            int idx = tid + i * 512;
            int brow = idx >> 2, bq = idx & 3;
            size_t gb = (size_t)(n0 + brow) * K + kc * BK + bq * 8;
            cp16(so + ATILE * 2 + (brow * LDSS + bq * 8) * 2, Bm + gb);
        }
        cp_commit();
    };

    issue(0, 0);
    if (nch > 1) issue(1, 1);

    for (int kc = 0; kc < nch; kc++) {
        if (kc + 1 < nch) cp_wait1(); else cp_wait0();
        __syncthreads();
        if (kc + 2 < nch) issue(kc + 2, (kc + 2) % GSTG);

        const uint32_t sa = sb + (uint32_t)(kc % GSTG) * STG_EL * 2;
        const uint32_t sA_ = sa;
        const uint32_t sB_ = sa + ATILE * 2;

#pragma unroll
        for (int ks = 0; ks < 2; ks++) {
            const int kb = ks * 16 + kq * 8;
            uint32_t af[2][4];
#pragma unroll
            for (int mi = 0; mi < 2; mi++) {
                uint32_t ad = ((wm + mi * 16 + l8 + half_ * 8) * LDSS + kb) * 2;
                ldsm4(af[mi], sA_ + ad);
            }
#pragma unroll
            for (int p = 0; p < 4; p++) {
                uint32_t bd = ((wn + p * 16 + l8 + half_ * 8) * LDSS + kb) * 2;
                uint32_t tb[4];
                ldsm4(tb, sB_ + bd);
                uint32_t be0[2] = {tb[0], tb[2]}, be1[2] = {tb[1], tb[3]};
#pragma unroll
                for (int mi = 0; mi < 2; mi++) {
                    mma_f16(acc[mi][2 * p],     af[mi], be0);
                    mma_f16(acc[mi][2 * p + 1], af[mi], be1);
                }
            }
        }
    }

#pragma unroll
    for (int mi = 0; mi < 2; mi++) {
        int r = m0 + wm + mi * 16 + g;
#pragma unroll
        for (int ni = 0; ni < 8; ni++) {
            int c = n0 + wn + ni * 8 + 2 * t;
            *(float2*)&C[(size_t)r * N + c] = make_float2(acc[mi][ni][0], acc[mi][ni][1]);
            *(float2*)&C[(size_t)(r + 8) * N + c] = make_float2(acc[mi][ni][2], acc[mi][ni][3]);
        }
    }
}

// ---------------------------------------------------------------------------
// RoPE table + fused rope-Q / rope-K / V-convert (one launch)
// ---------------------------------------------------------------------------
__global__ void rope_table_kernel() {
    int i = blockIdx.x * blockDim.x + threadIdx.x;
    int s = i >> 5, f = i & 31;
    double inv_freq = exp(-(double)f / 32.0 * log(10000.0));
    double sd, cd;
    sincos((double)s * inv_freq, &sd, &cd);
    g_rsin[i] = (float)sd;
    g_rcos[i] = (float)cd;
}

#define QN_ (M_TOT * NH_ * 32)    // 4,194,304
#define KN_ (M_TOT * NKV_ * 32)   // 1,048,576
#define VN_ (M_TOT * NKVD)        // 2,097,152

__global__ void rope_v_fused(const float* __restrict__ X,
                             __half* __restrict__ q16,
                             __half* __restrict__ k16,
                             __half* __restrict__ v16) {
    int idx0 = blockIdx.x * blockDim.x + threadIdx.x;
    if (idx0 < QN_) {
        int idx = idx0;
        int i = idx & 31;
        int bh = idx >> 5;
        int h = bh % NH_;
        int bs = bh / NH_;
        int s = bs & (S_ - 1);
        float c = g_rcos[s * 32 + i], sn = g_rsin[s * 32 + i];
        size_t sbase = (size_t)bs * NQKV + h * HD_;
        size_t dbase = (size_t)bs * HID_ + (size_t)h * HD_;
        float x1 = X[sbase + i], x2 = X[sbase + i + 32];
        q16[dbase + i]      = __float2half_rn(x1 * c - x2 * sn);
        q16[dbase + i + 32] = __float2half_rn(x2 * c + x1 * sn);
    } else if (idx0 < QN_ + KN_) {
        int idx = idx0 - QN_;
        int i = idx & 31;
        int bh = idx >> 5;
        int h = bh % NKV_;
        int bs = bh / NKV_;
        int s = bs & (S_ - 1);
        float c = g_rcos[s * 32 + i], sn = g_rsin[s * 32 + i];
        size_t sbase = (size_t)bs * NQKV + HID_ + h * HD_;
        size_t dbase = (size_t)bs * NKVD + (size_t)h * HD_;
        float x1 = X[sbase + i], x2 = X[sbase + i + 32];
        k16[dbase + i]      = __float2half_rn(x1 * c - x2 * sn);
        k16[dbase + i + 32] = __float2half_rn(x2 * c + x1 * sn);
    } else if (idx0 < QN_ + KN_ + VN_) {
        int idx = idx0 - (QN_ + KN_);
        int row = idx >> 9, col = idx & 511;
        v16[idx] = __float2half_rn(X[(size_t)row * NQKV + HID_ + NKVD + col]);
    }
}

// ---------------------------------------------------------------------------
// Flash attention: fp16 single-pass QK^T, fp16 single-pass PV.
// 2 smem buffers (K, V), 3-stage cp.async, launch_bounds(256,1).
// grid=(S/128, NH, B), heavy-first causal scheduling.
// ---------------------------------------------------------------------------
#define LDK 72
#define KVT (64 * LDK)
#define FSTG 3

__global__ void __launch_bounds__(256, 1) flash_mma(
    const __half* __restrict__ q16, const __half* __restrict__ k16,
    const __half* __restrict__ v16,
    __half* __restrict__ c16)
{
    extern __shared__ __half fdyn[];   // FSTG x 2 x KVT

    const int tid = threadIdx.x;
    const int w = tid >> 5, lane = tid & 31;
    const int g = lane >> 2, t = lane & 3;
    const int l8 = lane & 7, half_ = (lane >> 3) & 1, kq = lane >> 4;
    const int qt = (gridDim.x - 1) - blockIdx.x;      // heavy CTAs first
    const int h = blockIdx.y, b = blockIdx.z;
    const int kvh = h / GROUP_;
    const int row_base = qt * 128 + w * 16;
    const float SCALE = 0.125f;
    const uint32_t sb = smem_u32(fdyn);

    uint32_t aq[4][4];
    {
        const __half* qb = q16 + ((size_t)(b * S_ + row_base)) * HID_ + h * HD_;
#pragma unroll
        for (int j = 0; j < 4; j++) {
            int k0 = j * 16 + 2 * t;
            aq[j][0] = *(const uint32_t*)&qb[(size_t)g * HID_ + k0];
            aq[j][1] = *(const uint32_t*)&qb[(size_t)(g + 8) * HID_ + k0];
            aq[j][2] = *(const uint32_t*)&qb[(size_t)g * HID_ + k0 + 8];
            aq[j][3] = *(const uint32_t*)&qb[(size_t)(g + 8) * HID_ + k0 + 8];
        }
    }

    float o[8][4];
#pragma unroll
    for (int i = 0; i < 8; i++)
#pragma unroll
        for (int j = 0; j < 4; j++) o[i][j] = 0.f;
    float m0 = -INFINITY, m1 = -INFINITY, l0 = 0.f, l1 = 0.f;

    const int ntiles = 2 * qt + 2;

    auto issue = [&](int kt, int st) {
        uint32_t so = sb + (uint32_t)st * 2 * KVT * 2;
#pragma unroll
        for (int i = 0; i < 2; i++) {
            int idx = tid + i * 256;
            int r = idx >> 3, q = idx & 7;
            size_t go = ((size_t)(b * S_ + kt * 64 + r)) * NKVD + kvh * HD_ + q * 8;
            uint32_t off = (r * LDK + q * 8) * 2;
            cp16(so + off,           k16 + go);
            cp16(so + KVT * 2 + off, v16 + go);
        }
        cp_commit();
    };

    issue(0, 0);
    if (ntiles > 1) issue(1, 1);

    for (int kt = 0; kt < ntiles; kt++) {
        if (kt + 1 < ntiles) cp_wait1(); else cp_wait0();
        __syncthreads();
        if (kt + 2 < ntiles) issue(kt + 2, (kt + 2) % FSTG);

        const uint32_t sg = sb + (uint32_t)(kt % FSTG) * 2 * KVT * 2;
        const uint32_t sK_ = sg;
        const uint32_t sV_ = sg + KVT * 2;

        const bool skip = (kt * 64) > (row_base + 15);
        if (!skip) {
            float s[8][4];
#pragma unroll
            for (int i = 0; i < 8; i++)
#pragma unroll
                for (int j = 0; j < 4; j++) s[i][j] = 0.f;
#pragma unroll
            for (int j = 0; j < 4; j++) {
                const int kb = j * 16 + kq * 8;
#pragma unroll
                for (int kp = 0; kp < 4; kp++) {
                    uint32_t ad = ((kp * 16 + l8 + half_ * 8) * LDK + kb) * 2;
                    uint32_t th[4];
                    ldsm4(th, sK_ + ad);
                    uint32_t be0[2] = {th[0], th[2]}, be1[2] = {th[1], th[3]};
                    mma_f16(s[2 * kp],     aq[j], be0);
                    mma_f16(s[2 * kp + 1], aq[j], be1);
                }
            }
            const int r0 = row_base + g, r1 = row_base + g + 8;
#pragma unroll
            for (int ni = 0; ni < 8; ni++) {
                int c0 = kt * 64 + ni * 8 + 2 * t;
                s[ni][0] *= SCALE; s[ni][1] *= SCALE; s[ni][2] *= SCALE; s[ni][3] *= SCALE;
                if ((kt * 64 + 63) > r0 || (kt * 64 + 63) > r1) {
                    if (c0 > r0)     s[ni][0] = -INFINITY;
                    if (c0 + 1 > r0) s[ni][1] = -INFINITY;
                    if (c0 > r1)     s[ni][2] = -INFINITY;
                    if (c0 + 1 > r1) s[ni][3] = -INFINITY;
                }
            }
            float mx0 = -INFINITY, mx1 = -INFINITY;
#pragma unroll
            for (int ni = 0; ni < 8; ni++) {
                mx0 = fmaxf(mx0, fmaxf(s[ni][0], s[ni][1]));
                mx1 = fmaxf(mx1, fmaxf(s[ni][2], s[ni][3]));
            }
            mx0 = fmaxf(mx0, __shfl_xor_sync(0xffffffff, mx0, 1));
            mx0 = fmaxf(mx0, __shfl_xor_sync(0xffffffff, mx0, 2));
            mx1 = fmaxf(mx1, __shfl_xor_sync(0xffffffff, mx1, 1));
            mx1 = fmaxf(mx1, __shfl_xor_sync(0xffffffff, mx1, 2));

            float mn0 = fmaxf(m0, mx0), mn1 = fmaxf(m1, mx1);
            float f0 = __expf(m0 - mn0), f1 = __expf(m1 - mn1);
            m0 = mn0; m1 = mn1;

            float sum0 = 0.f, sum1 = 0.f;
#pragma unroll
            for (int ni = 0; ni < 8; ni++) {
                s[ni][0] = __expf(s[ni][0] - mn0);
                s[ni][1] = __expf(s[ni][1] - mn0);
                s[ni][2] = __expf(s[ni][2] - mn1);
                s[ni][3] = __expf(s[ni][3] - mn1);
                sum0 += s[ni][0] + s[ni][1];
                sum1 += s[ni][2] + s[ni][3];
            }
            sum0 += __shfl_xor_sync(0xffffffff, sum0, 1);
            sum0 += __shfl_xor_sync(0xffffffff, sum0, 2);
            sum1 += __shfl_xor_sync(0xffffffff, sum1, 1);
            sum1 += __shfl_xor_sync(0xffffffff, sum1, 2);
            l0 = l0 * f0 + sum0;
            l1 = l1 * f1 + sum1;

#pragma unroll
            for (int nd = 0; nd < 8; nd++) {
                o[nd][0] *= f0; o[nd][1] *= f0;
                o[nd][2] *= f1; o[nd][3] *= f1;
            }

            uint32_t pf[4][4];
#pragma unroll
            for (int j = 0; j < 4; j++) {
                pf[j][0] = pack_f16(s[2 * j][0],     s[2 * j][1]);
                pf[j][1] = pack_f16(s[2 * j][2],     s[2 * j][3]);
                pf[j][2] = pack_f16(s[2 * j + 1][0], s[2 * j + 1][1]);
                pf[j][3] = pack_f16(s[2 * j + 1][2], s[2 * j + 1][3]);
            }

#pragma unroll
            for (int j = 0; j < 4; j++) {
#pragma unroll
                for (int dp = 0; dp < 4; dp++) {
                    uint32_t ad = ((j * 16 + kq * 8 + l8) * LDK + dp * 16 + half_ * 8) * 2;
                    uint32_t th[4];
                    ldsm4t(th, sV_ + ad);
                    uint32_t b0a[2] = {th[0], th[2]}, b1a[2] = {th[1], th[3]};
                    mma_f16(o[2 * dp],     pf[j], b0a);
                    mma_f16(o[2 * dp + 1], pf[j], b1a);
                }
            }
        }
    }

    // --- normalize and write fp16 context ---
    float li0 = 1.0f / l0, li1 = 1.0f / l1;
    const size_t r0 = (size_t)(b * S_ + row_base + g) * HID_ + h * HD_;
    const size_t r1 = (size_t)(b * S_ + row_base + g + 8) * HID_ + h * HD_;
#pragma unroll
    for (int nd = 0; nd < 8; nd++) {
        int c = nd * 8 + 2 * t;
        *(uint32_t*)&c16[r0 + c] = pack_f16(o[nd][0] * li0, o[nd][1] * li0);
        *(uint32_t*)&c16[r1 + c] = pack_f16(o[nd][2] * li1, o[nd][3] * li1);
    }
}

// ---------------------------------------------------------------------------
// Launch
// ---------------------------------------------------------------------------
extern "C" void kernel_launch(void* const* d_in, const int* in_sizes, int n_in,
                              void* d_out, int out_size)
{
    const float* hidden = (const float*)d_in[0];
    const float* wq = (const float*)d_in[2];
    const float* wk = (const float*)d_in[3];
    const float* wv = (const float*)d_in[4];
    const float* wo = (const float*)d_in[5];
    float* out = (float*)d_out;

    float* qkv;
    cudaGetSymbolAddress((void**)&qkv, g_QKV);

    __half *h16, *wc16, *wo16, *q16, *k16, *v16, *c16;
    cudaGetSymbolAddress((void**)&h16, g_h16);
    cudaGetSymbolAddress((void**)&wc16, g_wc16); cudaGetSymbolAddress((void**)&wo16, g_wo16);
    cudaGetSymbolAddress((void**)&q16, g_q16);   cudaGetSymbolAddress((void**)&k16, g_k16);
    cudaGetSymbolAddress((void**)&v16, g_v16);   cudaGetSymbolAddress((void**)&c16, g_c16);

    const int GEMM_DYN = GSTG * STG_EL * 2;      // 92160 B
    const int FLASH_DYN = FSTG * 2 * KVT * 2;    // 55296 B
    cudaFuncSetAttribute(gemm_mma, cudaFuncAttributeMaxDynamicSharedMemorySize, GEMM_DYN);
    cudaFuncSetAttribute(flash_mma, cudaFuncAttributeMaxDynamicSharedMemorySize, FLASH_DYN);

    // Fused converts (one launch) + rope table
    conv_all<<<(CTOT + 255) / 256, 256>>>(hidden, wq, wk, wv, wo, h16, wc16, wo16);
    rope_table_kernel<<<(S_ * 32) / 256, 256>>>();

    // Fused QKV projection (fp16 1-pass)
    gemm_mma<<<dim3(NQKV / BN, M_TOT / BM), 512, GEMM_DYN>>>(h16, wc16, qkv, M_TOT, NQKV, HID_);

    // Fused RoPE-Q / RoPE-K / V-convert (one launch)
    rope_v_fused<<<(QN_ + KN_ + VN_ + 255) / 256, 256>>>(qkv, q16, k16, v16);

    // Flash attention (fp16 1-pass QK + 1-pass PV; writes fp16 ctx)
    flash_mma<<<dim3(S_ / 128, NH_, B_), 256, FLASH_DYN>>>(q16, k16, v16, c16);

    // O projection (fp16 1-pass)
    gemm_mma<<<dim3(HID_ / BN, M_TOT / BM), 512, GEMM_DYN>>>(c16, wo16, out, M_TOT, HID_, HID_);
}

// round 15
// speedup vs baseline: 2.9260x; 1.0096x over previous
#include <cuda_runtime.h>
#include <cuda_bf16.h>
#include <cuda_fp16.h>
#include <cstdint>
#include <math.h>

// Problem constants
#define B_   2
#define S_   2048
#define HID_ 2048
#define NH_  32
#define NKV_ 8
#define HD_  64
#define GROUP_ 4
#define M_TOT (B_ * S_)          // 4096
#define NKVD (NKV_ * HD_)        // 512
#define NQKV (HID_ + 2 * NKVD)   // 3072

// ---------------------------------------------------------------------------
// Scratch (__device__ globals; no cudaMalloc allowed)
// ---------------------------------------------------------------------------
__device__ __half g_h16[(size_t)M_TOT * HID_];    // hidden fp16
__device__ __half g_wc16[(size_t)NQKV * HID_];    // wq|wk|wv fp16
__device__ __half g_wo16[(size_t)HID_ * HID_];    // wo fp16
__device__ __half g_q16[(size_t)M_TOT * HID_];
__device__ __half g_k16[(size_t)M_TOT * NKVD];
__device__ __half g_v16[(size_t)M_TOT * NKVD];
__device__ __half g_c16[(size_t)M_TOT * HID_];    // ctx fp16

__device__ float g_rsin[S_ * 32], g_rcos[S_ * 32];

// ---------------------------------------------------------------------------
// Helpers
// ---------------------------------------------------------------------------
__device__ __forceinline__ uint32_t smem_u32(const void* p) {
    uint32_t a;
    asm("{ .reg .u64 t; cvta.to.shared.u64 t, %1; cvt.u32.u64 %0, t; }" : "=r"(a) : "l"(p));
    return a;
}
__device__ __forceinline__ void cp16(uint32_t dst, const void* src) {
    asm volatile("cp.async.cg.shared.global [%0], [%1], 16;" :: "r"(dst), "l"(src));
}
__device__ __forceinline__ void cp_commit() { asm volatile("cp.async.commit_group;"); }
__device__ __forceinline__ void cp_wait1() { asm volatile("cp.async.wait_group 1;"); }
__device__ __forceinline__ void cp_wait0() { asm volatile("cp.async.wait_group 0;"); }
__device__ __forceinline__ void ldsm4(uint32_t* r, uint32_t addr) {
    asm volatile("ldmatrix.sync.aligned.m8n8.x4.shared.b16 {%0,%1,%2,%3}, [%4];"
        : "=r"(r[0]), "=r"(r[1]), "=r"(r[2]), "=r"(r[3]) : "r"(addr));
}
__device__ __forceinline__ void ldsm4t(uint32_t* r, uint32_t addr) {
    asm volatile("ldmatrix.sync.aligned.m8n8.x4.trans.shared.b16 {%0,%1,%2,%3}, [%4];"
        : "=r"(r[0]), "=r"(r[1]), "=r"(r[2]), "=r"(r[3]) : "r"(addr));
}
__device__ __forceinline__ void mma_f16(float* c, const uint32_t* a, const uint32_t* b) {
    asm volatile(
        "mma.sync.aligned.m16n8k16.row.col.f32.f16.f16.f32 "
        "{%0,%1,%2,%3}, {%4,%5,%6,%7}, {%8,%9}, {%0,%1,%2,%3};"
        : "+f"(c[0]), "+f"(c[1]), "+f"(c[2]), "+f"(c[3])
        : "r"(a[0]), "r"(a[1]), "r"(a[2]), "r"(a[3]), "r"(b[0]), "r"(b[1]));
}
__device__ __forceinline__ uint32_t pack_f16(float x, float y) {
    __half2 h = __floats2half2_rn(x, y);
    return *(uint32_t*)&h;
}

// ---------------------------------------------------------------------------
// Fused convert: hidden + wq + wk + wv + wo -> fp16, one launch
// ---------------------------------------------------------------------------
#define CN1 (M_TOT * HID_)
#define CN2 (HID_ * HID_)
#define CN3 (NKVD * HID_)
#define CN4 (NKVD * HID_)
#define CN5 (HID_ * HID_)
#define CTOT (CN1 + CN2 + CN3 + CN4 + CN5)

__global__ void conv_all(const float* __restrict__ hidden,
                         const float* __restrict__ wq, const float* __restrict__ wk,
                         const float* __restrict__ wv, const float* __restrict__ wo,
                         __half* __restrict__ h16, __half* __restrict__ wc16,
                         __half* __restrict__ wo16) {
    int i = blockIdx.x * blockDim.x + threadIdx.x;
    if (i < CN1) {
        h16[i] = __float2half_rn(hidden[i]);
    } else if (i < CN1 + CN2) {
        int j = i - CN1;
        wc16[j] = __float2half_rn(wq[j]);
    } else if (i < CN1 + CN2 + CN3) {
        int j = i - (CN1 + CN2);
        wc16[CN2 + j] = __float2half_rn(wk[j]);
    } else if (i < CN1 + CN2 + CN3 + CN4) {
        int j = i - (CN1 + CN2 + CN3);
        wc16[CN2 + CN3 + j] = __float2half_rn(wv[j]);
    } else if (i < CTOT) {
        int j = i - (CN1 + CN2 + CN3 + CN4);
        wo16[j] = __float2half_rn(wo[j]);
    }
}

// ---------------------------------------------------------------------------
// RoPE table
// ---------------------------------------------------------------------------
__global__ void rope_table_kernel() {
    int i = blockIdx.x * blockDim.x + threadIdx.x;
    int s = i >> 5, f = i & 31;
    double inv_freq = exp(-(double)f / 32.0 * log(10000.0));
    double sd, cd;
    sincos((double)s * inv_freq, &sd, &cd);
    g_rsin[i] = (float)sd;
    g_rcos[i] = (float)cd;
}

// ---------------------------------------------------------------------------
// fp16 single-pass GEMM: C = A[M,K] * B[N,K]^T.
// mode 0: fp32 output to C.
// mode 1: fused QKV epilogue — per-warp head-aligned RoPE (register-local
//         d <-> d+32 pairing via acc[ni] <-> acc[ni+4]) + fp16 store to
//         q16/k16/v16.
// CTA 128x256x32, 512 thr (16 warps, warp 32x64), 3-stage cp.async.
// ---------------------------------------------------------------------------
#define BM 128
#define BN 256
#define BK 32
#define LDSS 40
#define ATILE (BM * LDSS)
#define BTILE (BN * LDSS)
#define STG_EL (ATILE + BTILE)
#define GSTG 3

__global__ void __launch_bounds__(512, 1) gemm_mma(
    const __half* __restrict__ Am, const __half* __restrict__ Bm,
    float* __restrict__ C,
    __half* __restrict__ q16, __half* __restrict__ k16, __half* __restrict__ v16,
    int mode, int M, int N, int K)
{
    extern __shared__ __half dyn[];

    const int tid = threadIdx.x;
    const int warp = tid >> 5, lane = tid & 31;
    const int wm = (warp >> 2) * 32;
    const int wn = (warp & 3) * 64;
    const int g = lane >> 2, t = lane & 3;
    const int l8 = lane & 7, half_ = (lane >> 3) & 1, kq = lane >> 4;
    const int m0 = blockIdx.y * BM, n0 = blockIdx.x * BN;

    const uint32_t sb = smem_u32(dyn);
    const int arow = tid >> 2, aq = tid & 3;

    float acc[2][8][4];
#pragma unroll
    for (int i = 0; i < 2; i++)
#pragma unroll
        for (int j = 0; j < 8; j++)
#pragma unroll
            for (int x = 0; x < 4; x++) acc[i][j][x] = 0.f;

    const int nch = K / BK;

    auto issue = [&](int kc, int st) {
        uint32_t so = sb + (uint32_t)st * STG_EL * 2;
        size_t ga = (size_t)(m0 + arow) * K + kc * BK + aq * 8;
        cp16(so + (arow * LDSS + aq * 8) * 2, Am + ga);
#pragma unroll
        for (int i = 0; i < 2; i++) {
            int idx = tid + i * 512;
            int brow = idx >> 2, bq = idx & 3;
            size_t gb = (size_t)(n0 + brow) * K + kc * BK + bq * 8;
            cp16(so + ATILE * 2 + (brow * LDSS + bq * 8) * 2, Bm + gb);
        }
        cp_commit();
    };

    issue(0, 0);
    if (nch > 1) issue(1, 1);

    for (int kc = 0; kc < nch; kc++) {
        if (kc + 1 < nch) cp_wait1(); else cp_wait0();
        __syncthreads();
        if (kc + 2 < nch) issue(kc + 2, (kc + 2) % GSTG);

        const uint32_t sa = sb + (uint32_t)(kc % GSTG) * STG_EL * 2;
        const uint32_t sA_ = sa;
        const uint32_t sB_ = sa + ATILE * 2;

#pragma unroll
        for (int ks = 0; ks < 2; ks++) {
            const int kb = ks * 16 + kq * 8;
            uint32_t af[2][4];
#pragma unroll
            for (int mi = 0; mi < 2; mi++) {
                uint32_t ad = ((wm + mi * 16 + l8 + half_ * 8) * LDSS + kb) * 2;
                ldsm4(af[mi], sA_ + ad);
            }
#pragma unroll
            for (int p = 0; p < 4; p++) {
                uint32_t bd = ((wn + p * 16 + l8 + half_ * 8) * LDSS + kb) * 2;
                uint32_t tb[4];
                ldsm4(tb, sB_ + bd);
                uint32_t be0[2] = {tb[0], tb[2]}, be1[2] = {tb[1], tb[3]};
#pragma unroll
                for (int mi = 0; mi < 2; mi++) {
                    mma_f16(acc[mi][2 * p],     af[mi], be0);
                    mma_f16(acc[mi][2 * p + 1], af[mi], be1);
                }
            }
        }
    }

    if (mode == 0) {
#pragma unroll
        for (int mi = 0; mi < 2; mi++) {
            int r = m0 + wm + mi * 16 + g;
#pragma unroll
            for (int ni = 0; ni < 8; ni++) {
                int c = n0 + wn + ni * 8 + 2 * t;
                *(float2*)&C[(size_t)r * N + c] = make_float2(acc[mi][ni][0], acc[mi][ni][1]);
                *(float2*)&C[(size_t)(r + 8) * N + c] = make_float2(acc[mi][ni][2], acc[mi][ni][3]);
            }
        }
    } else {
        // Fused QKV epilogue. Warp column span = exactly one 64-wide head.
        const int cbase = n0 + wn;       // 64-aligned; region boundaries too
        __half* dst;
        int stride, coff;
        bool dorope;
        if (cbase < HID_) {
            dst = q16; stride = HID_; coff = cbase; dorope = true;
        } else if (cbase < HID_ + NKVD) {
            dst = k16; stride = NKVD; coff = cbase - HID_; dorope = true;
        } else {
            dst = v16; stride = NKVD; coff = cbase - HID_ - NKVD; dorope = false;
        }
#pragma unroll
        for (int mi = 0; mi < 2; mi++) {
            int r = m0 + wm + mi * 16 + g;     // global row (b*S + s)
            int s0 = r & (S_ - 1);             // row r's seq pos
            int s1 = s0 + 8;                   // row r+8 (same batch: 128-aligned tiles)
            if (dorope) {
#pragma unroll
                for (int ni = 0; ni < 4; ni++) {
                    int d0 = ni * 8 + 2 * t;   // 0..30 (pairs with d0+32)
                    float cA0 = g_rcos[s0 * 32 + d0],     sA0 = g_rsin[s0 * 32 + d0];
                    float cA1 = g_rcos[s0 * 32 + d0 + 1], sA1 = g_rsin[s0 * 32 + d0 + 1];
                    float cB0 = g_rcos[s1 * 32 + d0],     sB0 = g_rsin[s1 * 32 + d0];
                    float cB1 = g_rcos[s1 * 32 + d0 + 1], sB1 = g_rsin[s1 * 32 + d0 + 1];
                    float x1a = acc[mi][ni][0], x1b = acc[mi][ni][1];
                    float x2a = acc[mi][ni + 4][0], x2b = acc[mi][ni + 4][1];
                    float x1c = acc[mi][ni][2], x1d = acc[mi][ni][3];
                    float x2c = acc[mi][ni + 4][2], x2d = acc[mi][ni + 4][3];
                    size_t rowA = (size_t)r * stride + coff;
                    size_t rowB = (size_t)(r + 8) * stride + coff;
                    *(uint32_t*)&dst[rowA + d0] =
                        pack_f16(x1a * cA0 - x2a * sA0, x1b * cA1 - x2b * sA1);
                    *(uint32_t*)&dst[rowA + d0 + 32] =
                        pack_f16(x2a * cA0 + x1a * sA0, x2b * cA1 + x1b * sA1);
                    *(uint32_t*)&dst[rowB + d0] =
                        pack_f16(x1c * cB0 - x2c * sB0, x1d * cB1 - x2d * sB1);
                    *(uint32_t*)&dst[rowB + d0 + 32] =
                        pack_f16(x2c * cB0 + x1c * sB0, x2d * cB1 + x1d * sB1);
                }
            } else {
#pragma unroll
                for (int ni = 0; ni < 8; ni++) {
                    int c = coff + ni * 8 + 2 * t;
                    *(uint32_t*)&dst[(size_t)r * stride + c] =
                        pack_f16(acc[mi][ni][0], acc[mi][ni][1]);
                    *(uint32_t*)&dst[(size_t)(r + 8) * stride + c] =
                        pack_f16(acc[mi][ni][2], acc[mi][ni][3]);
                }
            }
        }
    }
}

// ---------------------------------------------------------------------------
// Flash attention: fp16 single-pass QK^T, fp16 single-pass PV.
// 2 smem buffers (K, V), 3-stage cp.async, launch_bounds(256,1).
// grid=(S/128, NH, B), heavy-first causal scheduling.
// ---------------------------------------------------------------------------
#define LDK 72
#define KVT (64 * LDK)
#define FSTG 3

__global__ void __launch_bounds__(256, 1) flash_mma(
    const __half* __restrict__ q16, const __half* __restrict__ k16,
    const __half* __restrict__ v16,
    __half* __restrict__ c16)
{
    extern __shared__ __half fdyn[];   // FSTG x 2 x KVT

    const int tid = threadIdx.x;
    const int w = tid >> 5, lane = tid & 31;
    const int g = lane >> 2, t = lane & 3;
    const int l8 = lane & 7, half_ = (lane >> 3) & 1, kq = lane >> 4;
    const int qt = (gridDim.x - 1) - blockIdx.x;      // heavy CTAs first
    const int h = blockIdx.y, b = blockIdx.z;
    const int kvh = h / GROUP_;
    const int row_base = qt * 128 + w * 16;
    const float SCALE = 0.125f;
    const uint32_t sb = smem_u32(fdyn);

    uint32_t aq[4][4];
    {
        const __half* qb = q16 + ((size_t)(b * S_ + row_base)) * HID_ + h * HD_;
#pragma unroll
        for (int j = 0; j < 4; j++) {
            int k0 = j * 16 + 2 * t;
            aq[j][0] = *(const uint32_t*)&qb[(size_t)g * HID_ + k0];
            aq[j][1] = *(const uint32_t*)&qb[(size_t)(g + 8) * HID_ + k0];
            aq[j][2] = *(const uint32_t*)&qb[(size_t)g * HID_ + k0 + 8];
            aq[j][3] = *(const uint32_t*)&qb[(size_t)(g + 8) * HID_ + k0 + 8];
        }
    }

    float o[8][4];
#pragma unroll
    for (int i = 0; i < 8; i++)
#pragma unroll
        for (int j = 0; j < 4; j++) o[i][j] = 0.f;
    float m0 = -INFINITY, m1 = -INFINITY, l0 = 0.f, l1 = 0.f;

    const int ntiles = 2 * qt + 2;

    auto issue = [&](int kt, int st) {
        uint32_t so = sb + (uint32_t)st * 2 * KVT * 2;
#pragma unroll
        for (int i = 0; i < 2; i++) {
            int idx = tid + i * 256;
            int r = idx >> 3, q = idx & 7;
            size_t go = ((size_t)(b * S_ + kt * 64 + r)) * NKVD + kvh * HD_ + q * 8;
            uint32_t off = (r * LDK + q * 8) * 2;
            cp16(so + off,           k16 + go);
            cp16(so + KVT * 2 + off, v16 + go);
        }
        cp_commit();
    };

    issue(0, 0);
    if (ntiles > 1) issue(1, 1);

    for (int kt = 0; kt < ntiles; kt++) {
        if (kt + 1 < ntiles) cp_wait1(); else cp_wait0();
        __syncthreads();
        if (kt + 2 < ntiles) issue(kt + 2, (kt + 2) % FSTG);

        const uint32_t sg = sb + (uint32_t)(kt % FSTG) * 2 * KVT * 2;
        const uint32_t sK_ = sg;
        const uint32_t sV_ = sg + KVT * 2;

        const bool skip = (kt * 64) > (row_base + 15);
        if (!skip) {
            float s[8][4];
#pragma unroll
            for (int i = 0; i < 8; i++)
#pragma unroll
                for (int j = 0; j < 4; j++) s[i][j] = 0.f;
#pragma unroll
            for (int j = 0; j < 4; j++) {
                const int kb = j * 16 + kq * 8;
#pragma unroll
                for (int kp = 0; kp < 4; kp++) {
                    uint32_t ad = ((kp * 16 + l8 + half_ * 8) * LDK + kb) * 2;
                    uint32_t th[4];
                    ldsm4(th, sK_ + ad);
                    uint32_t be0[2] = {th[0], th[2]}, be1[2] = {th[1], th[3]};
                    mma_f16(s[2 * kp],     aq[j], be0);
                    mma_f16(s[2 * kp + 1], aq[j], be1);
                }
            }
            const int r0 = row_base + g, r1 = row_base + g + 8;
#pragma unroll
            for (int ni = 0; ni < 8; ni++) {
                int c0 = kt * 64 + ni * 8 + 2 * t;
                s[ni][0] *= SCALE; s[ni][1] *= SCALE; s[ni][2] *= SCALE; s[ni][3] *= SCALE;
                if ((kt * 64 + 63) > r0 || (kt * 64 + 63) > r1) {
                    if (c0 > r0)     s[ni][0] = -INFINITY;
                    if (c0 + 1 > r0) s[ni][1] = -INFINITY;
                    if (c0 > r1)     s[ni][2] = -INFINITY;
                    if (c0 + 1 > r1) s[ni][3] = -INFINITY;
                }
            }
            float mx0 = -INFINITY, mx1 = -INFINITY;
#pragma unroll
            for (int ni = 0; ni < 8; ni++) {
                mx0 = fmaxf(mx0, fmaxf(s[ni][0], s[ni][1]));
                mx1 = fmaxf(mx1, fmaxf(s[ni][2], s[ni][3]));
            }
            mx0 = fmaxf(mx0, __shfl_xor_sync(0xffffffff, mx0, 1));
            mx0 = fmaxf(mx0, __shfl_xor_sync(0xffffffff, mx0, 2));
            mx1 = fmaxf(mx1, __shfl_xor_sync(0xffffffff, mx1, 1));
            mx1 = fmaxf(mx1, __shfl_xor_sync(0xffffffff, mx1, 2));

            float mn0 = fmaxf(m0, mx0), mn1 = fmaxf(m1, mx1);
            float f0 = __expf(m0 - mn0), f1 = __expf(m1 - mn1);
            m0 = mn0; m1 = mn1;

            float sum0 = 0.f, sum1 = 0.f;
#pragma unroll
            for (int ni = 0; ni < 8; ni++) {
                s[ni][0] = __expf(s[ni][0] - mn0);
                s[ni][1] = __expf(s[ni][1] - mn0);
                s[ni][2] = __expf(s[ni][2] - mn1);
                s[ni][3] = __expf(s[ni][3] - mn1);
                sum0 += s[ni][0] + s[ni][1];
                sum1 += s[ni][2] + s[ni][3];
            }
            sum0 += __shfl_xor_sync(0xffffffff, sum0, 1);
            sum0 += __shfl_xor_sync(0xffffffff, sum0, 2);
            sum1 += __shfl_xor_sync(0xffffffff, sum1, 1);
            sum1 += __shfl_xor_sync(0xffffffff, sum1, 2);
            l0 = l0 * f0 + sum0;
            l1 = l1 * f1 + sum1;

#pragma unroll
            for (int nd = 0; nd < 8; nd++) {
                o[nd][0] *= f0; o[nd][1] *= f0;
                o[nd][2] *= f1; o[nd][3] *= f1;
            }

            uint32_t pf[4][4];
#pragma unroll
            for (int j = 0; j < 4; j++) {
                pf[j][0] = pack_f16(s[2 * j][0],     s[2 * j][1]);
                pf[j][1] = pack_f16(s[2 * j][2],     s[2 * j][3]);
                pf[j][2] = pack_f16(s[2 * j + 1][0], s[2 * j + 1][1]);
                pf[j][3] = pack_f16(s[2 * j + 1][2], s[2 * j + 1][3]);
            }

#pragma unroll
            for (int j = 0; j < 4; j++) {
#pragma unroll
                for (int dp = 0; dp < 4; dp++) {
                    uint32_t ad = ((j * 16 + kq * 8 + l8) * LDK + dp * 16 + half_ * 8) * 2;
                    uint32_t th[4];
                    ldsm4t(th, sV_ + ad);
                    uint32_t b0a[2] = {th[0], th[2]}, b1a[2] = {th[1], th[3]};
                    mma_f16(o[2 * dp],     pf[j], b0a);
                    mma_f16(o[2 * dp + 1], pf[j], b1a);
                }
            }
        }
    }

    float li0 = 1.0f / l0, li1 = 1.0f / l1;
    const size_t r0 = (size_t)(b * S_ + row_base + g) * HID_ + h * HD_;
    const size_t r1 = (size_t)(b * S_ + row_base + g + 8) * HID_ + h * HD_;
#pragma unroll
    for (int nd = 0; nd < 8; nd++) {
        int c = nd * 8 + 2 * t;
        *(uint32_t*)&c16[r0 + c] = pack_f16(o[nd][0] * li0, o[nd][1] * li0);
        *(uint32_t*)&c16[r1 + c] = pack_f16(o[nd][2] * li1, o[nd][3] * li1);
    }
}

// ---------------------------------------------------------------------------
// Launch
// ---------------------------------------------------------------------------
extern "C" void kernel_launch(void* const* d_in, const int* in_sizes, int n_in,
                              void* d_out, int out_size)
{
    const float* hidden = (const float*)d_in[0];
    const float* wq = (const float*)d_in[2];
    const float* wk = (const float*)d_in[3];
    const float* wv = (const float*)d_in[4];
    const float* wo = (const float*)d_in[5];
    float* out = (float*)d_out;

    __half *h16, *wc16, *wo16, *q16, *k16, *v16, *c16;
    cudaGetSymbolAddress((void**)&h16, g_h16);
    cudaGetSymbolAddress((void**)&wc16, g_wc16); cudaGetSymbolAddress((void**)&wo16, g_wo16);
    cudaGetSymbolAddress((void**)&q16, g_q16);   cudaGetSymbolAddress((void**)&k16, g_k16);
    cudaGetSymbolAddress((void**)&v16, g_v16);   cudaGetSymbolAddress((void**)&c16, g_c16);

    const int GEMM_DYN = GSTG * STG_EL * 2;      // 92160 B
    const int FLASH_DYN = FSTG * 2 * KVT * 2;    // 55296 B
    cudaFuncSetAttribute(gemm_mma, cudaFuncAttributeMaxDynamicSharedMemorySize, GEMM_DYN);
    cudaFuncSetAttribute(flash_mma, cudaFuncAttributeMaxDynamicSharedMemorySize, FLASH_DYN);

    // Fused converts (one launch) + rope table
    conv_all<<<(CTOT + 255) / 256, 256>>>(hidden, wq, wk, wv, wo, h16, wc16, wo16);
    rope_table_kernel<<<(S_ * 32) / 256, 256>>>();

    // Fused QKV projection + RoPE epilogue (writes q16/k16/v16 directly)
    gemm_mma<<<dim3(NQKV / BN, M_TOT / BM), 512, GEMM_DYN>>>(
        h16, wc16, out /*unused*/, q16, k16, v16, 1, M_TOT, NQKV, HID_);

    // Flash attention (fp16 1-pass QK + 1-pass PV; writes fp16 ctx)
    flash_mma<<<dim3(S_ / 128, NH_, B_), 256, FLASH_DYN>>>(q16, k16, v16, c16);

    // O projection (fp32 output)
    gemm_mma<<<dim3(HID_ / BN, M_TOT / BM), 512, GEMM_DYN>>>(
        c16, wo16, out, q16, k16, v16, 0, M_TOT, HID_, HID_);
}

// round 16
// speedup vs baseline: 3.0393x; 1.0387x over previous
#include <cuda_runtime.h>
#include <cuda_bf16.h>
#include <cuda_fp16.h>
#include <cstdint>
#include <math.h>

// Problem constants
#define B_   2
#define S_   2048
#define HID_ 2048
#define NH_  32
#define NKV_ 8
#define HD_  64
#define GROUP_ 4
#define M_TOT (B_ * S_)          // 4096
#define NKVD (NKV_ * HD_)        // 512
#define NQKV (HID_ + 2 * NKVD)   // 3072

// ---------------------------------------------------------------------------
// Scratch (__device__ globals; no cudaMalloc allowed)
// ---------------------------------------------------------------------------
__device__ __half g_h16[(size_t)M_TOT * HID_];    // hidden fp16
__device__ __half g_wc16[(size_t)NQKV * HID_];    // wq|wk|wv fp16
__device__ __half g_wo16[(size_t)HID_ * HID_];    // wo fp16
__device__ __half g_q16[(size_t)M_TOT * HID_];    // pre-scaled by 1/8
__device__ __half g_k16[(size_t)M_TOT * NKVD];
__device__ __half g_v16[(size_t)M_TOT * NKVD];
__device__ __half g_c16[(size_t)M_TOT * HID_];    // ctx fp16

__device__ float g_rsin[S_ * 32], g_rcos[S_ * 32];

// ---------------------------------------------------------------------------
// Helpers
// ---------------------------------------------------------------------------
__device__ __forceinline__ uint32_t smem_u32(const void* p) {
    uint32_t a;
    asm("{ .reg .u64 t; cvta.to.shared.u64 t, %1; cvt.u32.u64 %0, t; }" : "=r"(a) : "l"(p));
    return a;
}
__device__ __forceinline__ void cp16(uint32_t dst, const void* src) {
    asm volatile("cp.async.cg.shared.global [%0], [%1], 16;" :: "r"(dst), "l"(src));
}
__device__ __forceinline__ void cp_commit() { asm volatile("cp.async.commit_group;"); }
__device__ __forceinline__ void cp_wait1() { asm volatile("cp.async.wait_group 1;"); }
__device__ __forceinline__ void cp_wait0() { asm volatile("cp.async.wait_group 0;"); }
__device__ __forceinline__ void ldsm4(uint32_t* r, uint32_t addr) {
    asm volatile("ldmatrix.sync.aligned.m8n8.x4.shared.b16 {%0,%1,%2,%3}, [%4];"
        : "=r"(r[0]), "=r"(r[1]), "=r"(r[2]), "=r"(r[3]) : "r"(addr));
}
__device__ __forceinline__ void ldsm4t(uint32_t* r, uint32_t addr) {
    asm volatile("ldmatrix.sync.aligned.m8n8.x4.trans.shared.b16 {%0,%1,%2,%3}, [%4];"
        : "=r"(r[0]), "=r"(r[1]), "=r"(r[2]), "=r"(r[3]) : "r"(addr));
}
__device__ __forceinline__ void mma_f16(float* c, const uint32_t* a, const uint32_t* b) {
    asm volatile(
        "mma.sync.aligned.m16n8k16.row.col.f32.f16.f16.f32 "
        "{%0,%1,%2,%3}, {%4,%5,%6,%7}, {%8,%9}, {%0,%1,%2,%3};"
        : "+f"(c[0]), "+f"(c[1]), "+f"(c[2]), "+f"(c[3])
        : "r"(a[0]), "r"(a[1]), "r"(a[2]), "r"(a[3]), "r"(b[0]), "r"(b[1]));
}
__device__ __forceinline__ uint32_t pack_f16(float x, float y) {
    __half2 h = __floats2half2_rn(x, y);
    return *(uint32_t*)&h;
}

// ---------------------------------------------------------------------------
// Fused convert: hidden + wq + wk + wv + wo -> fp16, one launch
// ---------------------------------------------------------------------------
#define CN1 (M_TOT * HID_)
#define CN2 (HID_ * HID_)
#define CN3 (NKVD * HID_)
#define CN4 (NKVD * HID_)
#define CN5 (HID_ * HID_)
#define CTOT (CN1 + CN2 + CN3 + CN4 + CN5)

__global__ void conv_all(const float* __restrict__ hidden,
                         const float* __restrict__ wq, const float* __restrict__ wk,
                         const float* __restrict__ wv, const float* __restrict__ wo,
                         __half* __restrict__ h16, __half* __restrict__ wc16,
                         __half* __restrict__ wo16) {
    int i = blockIdx.x * blockDim.x + threadIdx.x;
    if (i < CN1) {
        h16[i] = __float2half_rn(hidden[i]);
    } else if (i < CN1 + CN2) {
        int j = i - CN1;
        wc16[j] = __float2half_rn(wq[j]);
    } else if (i < CN1 + CN2 + CN3) {
        int j = i - (CN1 + CN2);
        wc16[CN2 + j] = __float2half_rn(wk[j]);
    } else if (i < CN1 + CN2 + CN3 + CN4) {
        int j = i - (CN1 + CN2 + CN3);
        wc16[CN2 + CN3 + j] = __float2half_rn(wv[j]);
    } else if (i < CTOT) {
        int j = i - (CN1 + CN2 + CN3 + CN4);
        wo16[j] = __float2half_rn(wo[j]);
    }
}

// ---------------------------------------------------------------------------
// RoPE table
// ---------------------------------------------------------------------------
__global__ void rope_table_kernel() {
    int i = blockIdx.x * blockDim.x + threadIdx.x;
    int s = i >> 5, f = i & 31;
    double inv_freq = exp(-(double)f / 32.0 * log(10000.0));
    double sd, cd;
    sincos((double)s * inv_freq, &sd, &cd);
    g_rsin[i] = (float)sd;
    g_rcos[i] = (float)cd;
}

// ---------------------------------------------------------------------------
// fp16 single-pass GEMM: C = A[M,K] * B[N,K]^T.
// mode 0: fp32 output to C.
// mode 1: fused QKV epilogue — head-aligned RoPE + fp16 store. Q additionally
//         pre-scaled by 1/8 (exact; removes softmax scale from flash).
// CTA 128x256x32, 512 thr (16 warps, warp 32x64), 3-stage cp.async.
// ---------------------------------------------------------------------------
#define BM 128
#define BN 256
#define BK 32
#define LDSS 40
#define ATILE (BM * LDSS)
#define BTILE (BN * LDSS)
#define STG_EL (ATILE + BTILE)
#define GSTG 3

__global__ void __launch_bounds__(512, 1) gemm_mma(
    const __half* __restrict__ Am, const __half* __restrict__ Bm,
    float* __restrict__ C,
    __half* __restrict__ q16, __half* __restrict__ k16, __half* __restrict__ v16,
    int mode, int M, int N, int K)
{
    extern __shared__ __half dyn[];

    const int tid = threadIdx.x;
    const int warp = tid >> 5, lane = tid & 31;
    const int wm = (warp >> 2) * 32;
    const int wn = (warp & 3) * 64;
    const int g = lane >> 2, t = lane & 3;
    const int l8 = lane & 7, half_ = (lane >> 3) & 1, kq = lane >> 4;
    const int m0 = blockIdx.y * BM, n0 = blockIdx.x * BN;

    const uint32_t sb = smem_u32(dyn);
    const int arow = tid >> 2, aq = tid & 3;

    float acc[2][8][4];
#pragma unroll
    for (int i = 0; i < 2; i++)
#pragma unroll
        for (int j = 0; j < 8; j++)
#pragma unroll
            for (int x = 0; x < 4; x++) acc[i][j][x] = 0.f;

    const int nch = K / BK;

    auto issue = [&](int kc, int st) {
        uint32_t so = sb + (uint32_t)st * STG_EL * 2;
        size_t ga = (size_t)(m0 + arow) * K + kc * BK + aq * 8;
        cp16(so + (arow * LDSS + aq * 8) * 2, Am + ga);
#pragma unroll
        for (int i = 0; i < 2; i++) {
            int idx = tid + i * 512;
            int brow = idx >> 2, bq = idx & 3;
            size_t gb = (size_t)(n0 + brow) * K + kc * BK + bq * 8;
            cp16(so + ATILE * 2 + (brow * LDSS + bq * 8) * 2, Bm + gb);
        }
        cp_commit();
    };

    issue(0, 0);
    if (nch > 1) issue(1, 1);

    for (int kc = 0; kc < nch; kc++) {
        if (kc + 1 < nch) cp_wait1(); else cp_wait0();
        __syncthreads();
        if (kc + 2 < nch) issue(kc + 2, (kc + 2) % GSTG);

        const uint32_t sa = sb + (uint32_t)(kc % GSTG) * STG_EL * 2;
        const uint32_t sA_ = sa;
        const uint32_t sB_ = sa + ATILE * 2;

#pragma unroll
        for (int ks = 0; ks < 2; ks++) {
            const int kb = ks * 16 + kq * 8;
            uint32_t af[2][4];
#pragma unroll
            for (int mi = 0; mi < 2; mi++) {
                uint32_t ad = ((wm + mi * 16 + l8 + half_ * 8) * LDSS + kb) * 2;
                ldsm4(af[mi], sA_ + ad);
            }
#pragma unroll
            for (int p = 0; p < 4; p++) {
                uint32_t bd = ((wn + p * 16 + l8 + half_ * 8) * LDSS + kb) * 2;
                uint32_t tb[4];
                ldsm4(tb, sB_ + bd);
                uint32_t be0[2] = {tb[0], tb[2]}, be1[2] = {tb[1], tb[3]};
#pragma unroll
                for (int mi = 0; mi < 2; mi++) {
                    mma_f16(acc[mi][2 * p],     af[mi], be0);
                    mma_f16(acc[mi][2 * p + 1], af[mi], be1);
                }
            }
        }
    }

    if (mode == 0) {
#pragma unroll
        for (int mi = 0; mi < 2; mi++) {
            int r = m0 + wm + mi * 16 + g;
#pragma unroll
            for (int ni = 0; ni < 8; ni++) {
                int c = n0 + wn + ni * 8 + 2 * t;
                *(float2*)&C[(size_t)r * N + c] = make_float2(acc[mi][ni][0], acc[mi][ni][1]);
                *(float2*)&C[(size_t)(r + 8) * N + c] = make_float2(acc[mi][ni][2], acc[mi][ni][3]);
            }
        }
    } else {
        // Fused QKV epilogue. Warp column span = exactly one 64-wide head.
        const int cbase = n0 + wn;
        __half* dst;
        int stride, coff;
        bool dorope;
        float qs = 1.0f;
        if (cbase < HID_) {
            dst = q16; stride = HID_; coff = cbase; dorope = true;
            qs = 0.125f;                     // pre-scale Q by 1/sqrt(64): exact
        } else if (cbase < HID_ + NKVD) {
            dst = k16; stride = NKVD; coff = cbase - HID_; dorope = true;
        } else {
            dst = v16; stride = NKVD; coff = cbase - HID_ - NKVD; dorope = false;
        }
#pragma unroll
        for (int mi = 0; mi < 2; mi++) {
            int r = m0 + wm + mi * 16 + g;
            int s0 = r & (S_ - 1);
            int s1 = s0 + 8;
            if (dorope) {
#pragma unroll
                for (int ni = 0; ni < 4; ni++) {
                    int d0 = ni * 8 + 2 * t;
                    float cA0 = g_rcos[s0 * 32 + d0] * qs,     sA0 = g_rsin[s0 * 32 + d0] * qs;
                    float cA1 = g_rcos[s0 * 32 + d0 + 1] * qs, sA1 = g_rsin[s0 * 32 + d0 + 1] * qs;
                    float cB0 = g_rcos[s1 * 32 + d0] * qs,     sB0 = g_rsin[s1 * 32 + d0] * qs;
                    float cB1 = g_rcos[s1 * 32 + d0 + 1] * qs, sB1 = g_rsin[s1 * 32 + d0 + 1] * qs;
                    float x1a = acc[mi][ni][0], x1b = acc[mi][ni][1];
                    float x2a = acc[mi][ni + 4][0], x2b = acc[mi][ni + 4][1];
                    float x1c = acc[mi][ni][2], x1d = acc[mi][ni][3];
                    float x2c = acc[mi][ni + 4][2], x2d = acc[mi][ni + 4][3];
                    size_t rowA = (size_t)r * stride + coff;
                    size_t rowB = (size_t)(r + 8) * stride + coff;
                    *(uint32_t*)&dst[rowA + d0] =
                        pack_f16(x1a * cA0 - x2a * sA0, x1b * cA1 - x2b * sA1);
                    *(uint32_t*)&dst[rowA + d0 + 32] =
                        pack_f16(x2a * cA0 + x1a * sA0, x2b * cA1 + x1b * sA1);
                    *(uint32_t*)&dst[rowB + d0] =
                        pack_f16(x1c * cB0 - x2c * sB0, x1d * cB1 - x2d * sB1);
                    *(uint32_t*)&dst[rowB + d0 + 32] =
                        pack_f16(x2c * cB0 + x1c * sB0, x2d * cB1 + x1d * sB1);
                }
            } else {
#pragma unroll
                for (int ni = 0; ni < 8; ni++) {
                    int c = coff + ni * 8 + 2 * t;
                    *(uint32_t*)&dst[(size_t)r * stride + c] =
                        pack_f16(acc[mi][ni][0], acc[mi][ni][1]);
                    *(uint32_t*)&dst[(size_t)(r + 8) * stride + c] =
                        pack_f16(acc[mi][ni][2], acc[mi][ni][3]);
                }
            }
        }
    }
}

// ---------------------------------------------------------------------------
// Flash attention: fp16 single-pass QK^T (Q pre-scaled), fp16 single-pass PV.
// 2 smem buffers, 3-stage cp.async. 2 CTAs/SM (regs fit after scale removal).
// grid=(S/128, NH, B), heavy-first causal scheduling.
// ---------------------------------------------------------------------------
#define LDK 72
#define KVT (64 * LDK)
#define FSTG 3

__global__ void __launch_bounds__(256, 2) flash_mma(
    const __half* __restrict__ q16, const __half* __restrict__ k16,
    const __half* __restrict__ v16,
    __half* __restrict__ c16)
{
    extern __shared__ __half fdyn[];   // FSTG x 2 x KVT

    const int tid = threadIdx.x;
    const int w = tid >> 5, lane = tid & 31;
    const int g = lane >> 2, t = lane & 3;
    const int l8 = lane & 7, half_ = (lane >> 3) & 1, kq = lane >> 4;
    const int qt = (gridDim.x - 1) - blockIdx.x;      // heavy CTAs first
    const int h = blockIdx.y, b = blockIdx.z;
    const int kvh = h / GROUP_;
    const int row_base = qt * 128 + w * 16;
    const uint32_t sb = smem_u32(fdyn);

    uint32_t aq[4][4];
    {
        const __half* qb = q16 + ((size_t)(b * S_ + row_base)) * HID_ + h * HD_;
#pragma unroll
        for (int j = 0; j < 4; j++) {
            int k0 = j * 16 + 2 * t;
            aq[j][0] = *(const uint32_t*)&qb[(size_t)g * HID_ + k0];
            aq[j][1] = *(const uint32_t*)&qb[(size_t)(g + 8) * HID_ + k0];
            aq[j][2] = *(const uint32_t*)&qb[(size_t)g * HID_ + k0 + 8];
            aq[j][3] = *(const uint32_t*)&qb[(size_t)(g + 8) * HID_ + k0 + 8];
        }
    }

    float o[8][4];
#pragma unroll
    for (int i = 0; i < 8; i++)
#pragma unroll
        for (int j = 0; j < 4; j++) o[i][j] = 0.f;
    float m0 = -INFINITY, m1 = -INFINITY, l0 = 0.f, l1 = 0.f;

    const int ntiles = 2 * qt + 2;

    auto issue = [&](int kt, int st) {
        uint32_t so = sb + (uint32_t)st * 2 * KVT * 2;
#pragma unroll
        for (int i = 0; i < 2; i++) {
            int idx = tid + i * 256;
            int r = idx >> 3, q = idx & 7;
            size_t go = ((size_t)(b * S_ + kt * 64 + r)) * NKVD + kvh * HD_ + q * 8;
            uint32_t off = (r * LDK + q * 8) * 2;
            cp16(so + off,           k16 + go);
            cp16(so + KVT * 2 + off, v16 + go);
        }
        cp_commit();
    };

    issue(0, 0);
    if (ntiles > 1) issue(1, 1);

    for (int kt = 0; kt < ntiles; kt++) {
        if (kt + 1 < ntiles) cp_wait1(); else cp_wait0();
        __syncthreads();
        if (kt + 2 < ntiles) issue(kt + 2, (kt + 2) % FSTG);

        const uint32_t sg = sb + (uint32_t)(kt % FSTG) * 2 * KVT * 2;
        const uint32_t sK_ = sg;
        const uint32_t sV_ = sg + KVT * 2;

        const bool skip = (kt * 64) > (row_base + 15);
        if (!skip) {
            float s[8][4];
#pragma unroll
            for (int i = 0; i < 8; i++)
#pragma unroll
                for (int j = 0; j < 4; j++) s[i][j] = 0.f;
#pragma unroll
            for (int j = 0; j < 4; j++) {
                const int kb = j * 16 + kq * 8;
#pragma unroll
                for (int kp = 0; kp < 4; kp++) {
                    uint32_t ad = ((kp * 16 + l8 + half_ * 8) * LDK + kb) * 2;
                    uint32_t th[4];
                    ldsm4(th, sK_ + ad);
                    uint32_t be0[2] = {th[0], th[2]}, be1[2] = {th[1], th[3]};
                    mma_f16(s[2 * kp],     aq[j], be0);
                    mma_f16(s[2 * kp + 1], aq[j], be1);
                }
            }
            const int r0 = row_base + g, r1 = row_base + g + 8;
            // causal mask (scores already scaled: Q pre-scaled by 1/8)
#pragma unroll
            for (int ni = 0; ni < 8; ni++) {
                int c0 = kt * 64 + ni * 8 + 2 * t;
                if ((kt * 64 + 63) > r0 || (kt * 64 + 63) > r1) {
                    if (c0 > r0)     s[ni][0] = -INFINITY;
                    if (c0 + 1 > r0) s[ni][1] = -INFINITY;
                    if (c0 > r1)     s[ni][2] = -INFINITY;
                    if (c0 + 1 > r1) s[ni][3] = -INFINITY;
                }
            }
            float mx0 = -INFINITY, mx1 = -INFINITY;
#pragma unroll
            for (int ni = 0; ni < 8; ni++) {
                mx0 = fmaxf(mx0, fmaxf(s[ni][0], s[ni][1]));
                mx1 = fmaxf(mx1, fmaxf(s[ni][2], s[ni][3]));
            }
            mx0 = fmaxf(mx0, __shfl_xor_sync(0xffffffff, mx0, 1));
            mx0 = fmaxf(mx0, __shfl_xor_sync(0xffffffff, mx0, 2));
            mx1 = fmaxf(mx1, __shfl_xor_sync(0xffffffff, mx1, 1));
            mx1 = fmaxf(mx1, __shfl_xor_sync(0xffffffff, mx1, 2));

            float mn0 = fmaxf(m0, mx0), mn1 = fmaxf(m1, mx1);
            float f0 = __expf(m0 - mn0), f1 = __expf(m1 - mn1);
            m0 = mn0; m1 = mn1;

            float sum0 = 0.f, sum1 = 0.f;
#pragma unroll
            for (int ni = 0; ni < 8; ni++) {
                s[ni][0] = __expf(s[ni][0] - mn0);
                s[ni][1] = __expf(s[ni][1] - mn0);
                s[ni][2] = __expf(s[ni][2] - mn1);
                s[ni][3] = __expf(s[ni][3] - mn1);
                sum0 += s[ni][0] + s[ni][1];
                sum1 += s[ni][2] + s[ni][3];
            }
            sum0 += __shfl_xor_sync(0xffffffff, sum0, 1);
            sum0 += __shfl_xor_sync(0xffffffff, sum0, 2);
            sum1 += __shfl_xor_sync(0xffffffff, sum1, 1);
            sum1 += __shfl_xor_sync(0xffffffff, sum1, 2);
            l0 = l0 * f0 + sum0;
            l1 = l1 * f1 + sum1;

#pragma unroll
            for (int nd = 0; nd < 8; nd++) {
                o[nd][0] *= f0; o[nd][1] *= f0;
                o[nd][2] *= f1; o[nd][3] *= f1;
            }

            uint32_t pf[4][4];
#pragma unroll
            for (int j = 0; j < 4; j++) {
                pf[j][0] = pack_f16(s[2 * j][0],     s[2 * j][1]);
                pf[j][1] = pack_f16(s[2 * j][2],     s[2 * j][3]);
                pf[j][2] = pack_f16(s[2 * j + 1][0], s[2 * j + 1][1]);
                pf[j][3] = pack_f16(s[2 * j + 1][2], s[2 * j + 1][3]);
            }

#pragma unroll
            for (int j = 0; j < 4; j++) {
#pragma unroll
                for (int dp = 0; dp < 4; dp++) {
                    uint32_t ad = ((j * 16 + kq * 8 + l8) * LDK + dp * 16 + half_ * 8) * 2;
                    uint32_t th[4];
                    ldsm4t(th, sV_ + ad);
                    uint32_t b0a[2] = {th[0], th[2]}, b1a[2] = {th[1], th[3]};
                    mma_f16(o[2 * dp],     pf[j], b0a);
                    mma_f16(o[2 * dp + 1], pf[j], b1a);
                }
            }
        }
    }

    float li0 = 1.0f / l0, li1 = 1.0f / l1;
    const size_t r0 = (size_t)(b * S_ + row_base + g) * HID_ + h * HD_;
    const size_t r1 = (size_t)(b * S_ + row_base + g + 8) * HID_ + h * HD_;
#pragma unroll
    for (int nd = 0; nd < 8; nd++) {
        int c = nd * 8 + 2 * t;
        *(uint32_t*)&c16[r0 + c] = pack_f16(o[nd][0] * li0, o[nd][1] * li0);
        *(uint32_t*)&c16[r1 + c] = pack_f16(o[nd][2] * li1, o[nd][3] * li1);
    }
}

// ---------------------------------------------------------------------------
// Launch
// ---------------------------------------------------------------------------
extern "C" void kernel_launch(void* const* d_in, const int* in_sizes, int n_in,
                              void* d_out, int out_size)
{
    const float* hidden = (const float*)d_in[0];
    const float* wq = (const float*)d_in[2];
    const float* wk = (const float*)d_in[3];
    const float* wv = (const float*)d_in[4];
    const float* wo = (const float*)d_in[5];
    float* out = (float*)d_out;

    __half *h16, *wc16, *wo16, *q16, *k16, *v16, *c16;
    cudaGetSymbolAddress((void**)&h16, g_h16);
    cudaGetSymbolAddress((void**)&wc16, g_wc16); cudaGetSymbolAddress((void**)&wo16, g_wo16);
    cudaGetSymbolAddress((void**)&q16, g_q16);   cudaGetSymbolAddress((void**)&k16, g_k16);
    cudaGetSymbolAddress((void**)&v16, g_v16);   cudaGetSymbolAddress((void**)&c16, g_c16);

    const int GEMM_DYN = GSTG * STG_EL * 2;      // 92160 B
    const int FLASH_DYN = FSTG * 2 * KVT * 2;    // 55296 B
    cudaFuncSetAttribute(gemm_mma, cudaFuncAttributeMaxDynamicSharedMemorySize, GEMM_DYN);
    cudaFuncSetAttribute(flash_mma, cudaFuncAttributeMaxDynamicSharedMemorySize, FLASH_DYN);

    // Fused converts (one launch) + rope table
    conv_all<<<(CTOT + 255) / 256, 256>>>(hidden, wq, wk, wv, wo, h16, wc16, wo16);
    rope_table_kernel<<<(S_ * 32) / 256, 256>>>();

    // Fused QKV projection + RoPE epilogue (writes q16(scaled)/k16/v16)
    gemm_mma<<<dim3(NQKV / BN, M_TOT / BM), 512, GEMM_DYN>>>(
        h16, wc16, out /*unused*/, q16, k16, v16, 1, M_TOT, NQKV, HID_);

    // Flash attention (fp16; 2 CTAs/SM; writes fp16 ctx)
    flash_mma<<<dim3(S_ / 128, NH_, B_), 256, FLASH_DYN>>>(q16, k16, v16, c16);

    // O projection (fp32 output)
    gemm_mma<<<dim3(HID_ / BN, M_TOT / BM), 512, GEMM_DYN>>>(
        c16, wo16, out, q16, k16, v16, 0, M_TOT, HID_, HID_);
}

// round 17
// speedup vs baseline: 3.2241x; 1.0608x over previous
#include <cuda_runtime.h>
#include <cuda_bf16.h>
#include <cuda_fp16.h>
#include <cstdint>
#include <math.h>

// Problem constants
#define B_   2
#define S_   2048
#define HID_ 2048
#define NH_  32
#define NKV_ 8
#define HD_  64
#define GROUP_ 4
#define M_TOT (B_ * S_)          // 4096
#define NKVD (NKV_ * HD_)        // 512
#define NQKV (HID_ + 2 * NKVD)   // 3072

// ---------------------------------------------------------------------------
// Scratch (__device__ globals; no cudaMalloc allowed)
// ---------------------------------------------------------------------------
__device__ __half g_h16[(size_t)M_TOT * HID_];    // hidden fp16
__device__ __half g_wc16[(size_t)NQKV * HID_];    // wq|wk|wv fp16
__device__ __half g_wo16[(size_t)HID_ * HID_];    // wo fp16
__device__ __half g_q16[(size_t)M_TOT * HID_];    // pre-scaled by 0.125*log2(e)
__device__ __half g_k16[(size_t)M_TOT * NKVD];
__device__ __half g_v16[(size_t)M_TOT * NKVD];
__device__ __half g_c16[(size_t)M_TOT * HID_];    // ctx fp16

__device__ float g_rsin[S_ * 32], g_rcos[S_ * 32];

// ---------------------------------------------------------------------------
// Helpers
// ---------------------------------------------------------------------------
__device__ __forceinline__ uint32_t smem_u32(const void* p) {
    uint32_t a;
    asm("{ .reg .u64 t; cvta.to.shared.u64 t, %1; cvt.u32.u64 %0, t; }" : "=r"(a) : "l"(p));
    return a;
}
__device__ __forceinline__ void cp16(uint32_t dst, const void* src) {
    asm volatile("cp.async.cg.shared.global [%0], [%1], 16;" :: "r"(dst), "l"(src));
}
__device__ __forceinline__ void cp_commit() { asm volatile("cp.async.commit_group;"); }
__device__ __forceinline__ void cp_wait1() { asm volatile("cp.async.wait_group 1;"); }
__device__ __forceinline__ void cp_wait0() { asm volatile("cp.async.wait_group 0;"); }
__device__ __forceinline__ void ldsm4(uint32_t* r, uint32_t addr) {
    asm volatile("ldmatrix.sync.aligned.m8n8.x4.shared.b16 {%0,%1,%2,%3}, [%4];"
        : "=r"(r[0]), "=r"(r[1]), "=r"(r[2]), "=r"(r[3]) : "r"(addr));
}
__device__ __forceinline__ void ldsm4t(uint32_t* r, uint32_t addr) {
    asm volatile("ldmatrix.sync.aligned.m8n8.x4.trans.shared.b16 {%0,%1,%2,%3}, [%4];"
        : "=r"(r[0]), "=r"(r[1]), "=r"(r[2]), "=r"(r[3]) : "r"(addr));
}
__device__ __forceinline__ void mma_f16(float* c, const uint32_t* a, const uint32_t* b) {
    asm volatile(
        "mma.sync.aligned.m16n8k16.row.col.f32.f16.f16.f32 "
        "{%0,%1,%2,%3}, {%4,%5,%6,%7}, {%8,%9}, {%0,%1,%2,%3};"
        : "+f"(c[0]), "+f"(c[1]), "+f"(c[2]), "+f"(c[3])
        : "r"(a[0]), "r"(a[1]), "r"(a[2]), "r"(a[3]), "r"(b[0]), "r"(b[1]));
}
__device__ __forceinline__ uint32_t pack_f16(float x, float y) {
    __half2 h = __floats2half2_rn(x, y);
    return *(uint32_t*)&h;
}

// ---------------------------------------------------------------------------
// Fused convert (vectorized 4/thread): hidden + wq + wk + wv + wo -> fp16
// ---------------------------------------------------------------------------
#define CN1 (M_TOT * HID_)
#define CN2 (HID_ * HID_)
#define CN3 (NKVD * HID_)
#define CN4 (NKVD * HID_)
#define CN5 (HID_ * HID_)
#define CTOT (CN1 + CN2 + CN3 + CN4 + CN5)

__device__ __forceinline__ void conv4(const float* __restrict__ src,
                                      __half* __restrict__ dst, int j4) {
    float4 v = *(const float4*)(src + j4);
    __half2 lo = __floats2half2_rn(v.x, v.y);
    __half2 hi = __floats2half2_rn(v.z, v.w);
    uint2 pk = make_uint2(*(uint32_t*)&lo, *(uint32_t*)&hi);
    *(uint2*)(dst + j4) = pk;
}

__global__ void conv_all(const float* __restrict__ hidden,
                         const float* __restrict__ wq, const float* __restrict__ wk,
                         const float* __restrict__ wv, const float* __restrict__ wo,
                         __half* __restrict__ h16, __half* __restrict__ wc16,
                         __half* __restrict__ wo16) {
    int i4 = (blockIdx.x * blockDim.x + threadIdx.x) * 4;
    if (i4 < CN1) {
        conv4(hidden, h16, i4);
    } else if (i4 < CN1 + CN2) {
        conv4(wq, wc16, i4 - CN1);
    } else if (i4 < CN1 + CN2 + CN3) {
        conv4(wk, wc16 + CN2, i4 - (CN1 + CN2));
    } else if (i4 < CN1 + CN2 + CN3 + CN4) {
        conv4(wv, wc16 + CN2 + CN3, i4 - (CN1 + CN2 + CN3));
    } else if (i4 < CTOT) {
        conv4(wo, wo16, i4 - (CN1 + CN2 + CN3 + CN4));
    }
}

// ---------------------------------------------------------------------------
// RoPE table
// ---------------------------------------------------------------------------
__global__ void rope_table_kernel() {
    int i = blockIdx.x * blockDim.x + threadIdx.x;
    int s = i >> 5, f = i & 31;
    double inv_freq = exp(-(double)f / 32.0 * log(10000.0));
    double sd, cd;
    sincos((double)s * inv_freq, &sd, &cd);
    g_rsin[i] = (float)sd;
    g_rcos[i] = (float)cd;
}

// ---------------------------------------------------------------------------
// fp16 single-pass GEMM: C = A[M,K] * B[N,K]^T.
// mode 0: fp32 output. mode 1: fused QKV epilogue (RoPE + fp16 store;
// Q pre-scaled by 0.125*log2e so flash softmax runs in exp2 domain).
// CTA 128x256x32, 512 thr, 3-stage cp.async.
// ---------------------------------------------------------------------------
#define BM 128
#define BN 256
#define BK 32
#define LDSS 40
#define ATILE (BM * LDSS)
#define BTILE (BN * LDSS)
#define STG_EL (ATILE + BTILE)
#define GSTG 3
#define QSCALE 0.18033688011112042f   // 0.125 * log2(e)

__global__ void __launch_bounds__(512, 1) gemm_mma(
    const __half* __restrict__ Am, const __half* __restrict__ Bm,
    float* __restrict__ C,
    __half* __restrict__ q16, __half* __restrict__ k16, __half* __restrict__ v16,
    int mode, int M, int N, int K)
{
    extern __shared__ __half dyn[];

    const int tid = threadIdx.x;
    const int warp = tid >> 5, lane = tid & 31;
    const int wm = (warp >> 2) * 32;
    const int wn = (warp & 3) * 64;
    const int g = lane >> 2, t = lane & 3;
    const int l8 = lane & 7, half_ = (lane >> 3) & 1, kq = lane >> 4;
    const int m0 = blockIdx.y * BM, n0 = blockIdx.x * BN;

    const uint32_t sb = smem_u32(dyn);
    const int arow = tid >> 2, aq = tid & 3;

    float acc[2][8][4];
#pragma unroll
    for (int i = 0; i < 2; i++)
#pragma unroll
        for (int j = 0; j < 8; j++)
#pragma unroll
            for (int x = 0; x < 4; x++) acc[i][j][x] = 0.f;

    const int nch = K / BK;

    auto issue = [&](int kc, int st) {
        uint32_t so = sb + (uint32_t)st * STG_EL * 2;
        size_t ga = (size_t)(m0 + arow) * K + kc * BK + aq * 8;
        cp16(so + (arow * LDSS + aq * 8) * 2, Am + ga);
#pragma unroll
        for (int i = 0; i < 2; i++) {
            int idx = tid + i * 512;
            int brow = idx >> 2, bq = idx & 3;
            size_t gb = (size_t)(n0 + brow) * K + kc * BK + bq * 8;
            cp16(so + ATILE * 2 + (brow * LDSS + bq * 8) * 2, Bm + gb);
        }
        cp_commit();
    };

    issue(0, 0);
    if (nch > 1) issue(1, 1);

    for (int kc = 0; kc < nch; kc++) {
        if (kc + 1 < nch) cp_wait1(); else cp_wait0();
        __syncthreads();
        if (kc + 2 < nch) issue(kc + 2, (kc + 2) % GSTG);

        const uint32_t sa = sb + (uint32_t)(kc % GSTG) * STG_EL * 2;
        const uint32_t sA_ = sa;
        const uint32_t sB_ = sa + ATILE * 2;

#pragma unroll
        for (int ks = 0; ks < 2; ks++) {
            const int kb = ks * 16 + kq * 8;
            uint32_t af[2][4];
#pragma unroll
            for (int mi = 0; mi < 2; mi++) {
                uint32_t ad = ((wm + mi * 16 + l8 + half_ * 8) * LDSS + kb) * 2;
                ldsm4(af[mi], sA_ + ad);
            }
#pragma unroll
            for (int p = 0; p < 4; p++) {
                uint32_t bd = ((wn + p * 16 + l8 + half_ * 8) * LDSS + kb) * 2;
                uint32_t tb[4];
                ldsm4(tb, sB_ + bd);
                uint32_t be0[2] = {tb[0], tb[2]}, be1[2] = {tb[1], tb[3]};
#pragma unroll
                for (int mi = 0; mi < 2; mi++) {
                    mma_f16(acc[mi][2 * p],     af[mi], be0);
                    mma_f16(acc[mi][2 * p + 1], af[mi], be1);
                }
            }
        }
    }

    if (mode == 0) {
#pragma unroll
        for (int mi = 0; mi < 2; mi++) {
            int r = m0 + wm + mi * 16 + g;
#pragma unroll
            for (int ni = 0; ni < 8; ni++) {
                int c = n0 + wn + ni * 8 + 2 * t;
                *(float2*)&C[(size_t)r * N + c] = make_float2(acc[mi][ni][0], acc[mi][ni][1]);
                *(float2*)&C[(size_t)(r + 8) * N + c] = make_float2(acc[mi][ni][2], acc[mi][ni][3]);
            }
        }
    } else {
        // Fused QKV epilogue. Warp column span = exactly one 64-wide head.
        const int cbase = n0 + wn;
        __half* dst;
        int stride, coff;
        bool dorope;
        float qs = 1.0f;
        if (cbase < HID_) {
            dst = q16; stride = HID_; coff = cbase; dorope = true;
            qs = QSCALE;                 // 1/sqrt(64) * log2(e): exp2-domain scores
        } else if (cbase < HID_ + NKVD) {
            dst = k16; stride = NKVD; coff = cbase - HID_; dorope = true;
        } else {
            dst = v16; stride = NKVD; coff = cbase - HID_ - NKVD; dorope = false;
        }
#pragma unroll
        for (int mi = 0; mi < 2; mi++) {
            int r = m0 + wm + mi * 16 + g;
            int s0 = r & (S_ - 1);
            int s1 = s0 + 8;
            if (dorope) {
#pragma unroll
                for (int ni = 0; ni < 4; ni++) {
                    int d0 = ni * 8 + 2 * t;
                    float cA0 = g_rcos[s0 * 32 + d0] * qs,     sA0 = g_rsin[s0 * 32 + d0] * qs;
                    float cA1 = g_rcos[s0 * 32 + d0 + 1] * qs, sA1 = g_rsin[s0 * 32 + d0 + 1] * qs;
                    float cB0 = g_rcos[s1 * 32 + d0] * qs,     sB0 = g_rsin[s1 * 32 + d0] * qs;
                    float cB1 = g_rcos[s1 * 32 + d0 + 1] * qs, sB1 = g_rsin[s1 * 32 + d0 + 1] * qs;
                    float x1a = acc[mi][ni][0], x1b = acc[mi][ni][1];
                    float x2a = acc[mi][ni + 4][0], x2b = acc[mi][ni + 4][1];
                    float x1c = acc[mi][ni][2], x1d = acc[mi][ni][3];
                    float x2c = acc[mi][ni + 4][2], x2d = acc[mi][ni + 4][3];
                    size_t rowA = (size_t)r * stride + coff;
                    size_t rowB = (size_t)(r + 8) * stride + coff;
                    *(uint32_t*)&dst[rowA + d0] =
                        pack_f16(x1a * cA0 - x2a * sA0, x1b * cA1 - x2b * sA1);
                    *(uint32_t*)&dst[rowA + d0 + 32] =
                        pack_f16(x2a * cA0 + x1a * sA0, x2b * cA1 + x1b * sA1);
                    *(uint32_t*)&dst[rowB + d0] =
                        pack_f16(x1c * cB0 - x2c * sB0, x1d * cB1 - x2d * sB1);
                    *(uint32_t*)&dst[rowB + d0 + 32] =
                        pack_f16(x2c * cB0 + x1c * sB0, x2d * cB1 + x1d * sB1);
                }
            } else {
#pragma unroll
                for (int ni = 0; ni < 8; ni++) {
                    int c = coff + ni * 8 + 2 * t;
                    *(uint32_t*)&dst[(size_t)r * stride + c] =
                        pack_f16(acc[mi][ni][0], acc[mi][ni][1]);
                    *(uint32_t*)&dst[(size_t)(r + 8) * stride + c] =
                        pack_f16(acc[mi][ni][2], acc[mi][ni][3]);
                }
            }
        }
    }
}

// ---------------------------------------------------------------------------
// Flash attention: fp16 1-pass QK^T (scores in log2 domain), fp16 1-pass PV.
// exp2f softmax (no FMUL per exp). 2 smem buffers, 3-stage cp.async,
// 2 CTAs/SM. grid=(S/128, NH, B), heavy-first causal scheduling.
// ---------------------------------------------------------------------------
#define LDK 72
#define KVT (64 * LDK)
#define FSTG 3

__global__ void __launch_bounds__(256, 2) flash_mma(
    const __half* __restrict__ q16, const __half* __restrict__ k16,
    const __half* __restrict__ v16,
    __half* __restrict__ c16)
{
    extern __shared__ __half fdyn[];   // FSTG x 2 x KVT

    const int tid = threadIdx.x;
    const int w = tid >> 5, lane = tid & 31;
    const int g = lane >> 2, t = lane & 3;
    const int l8 = lane & 7, half_ = (lane >> 3) & 1, kq = lane >> 4;
    const int qt = (gridDim.x - 1) - blockIdx.x;      // heavy CTAs first
    const int h = blockIdx.y, b = blockIdx.z;
    const int kvh = h / GROUP_;
    const int row_base = qt * 128 + w * 16;
    const uint32_t sb = smem_u32(fdyn);

    uint32_t aq[4][4];
    {
        const __half* qb = q16 + ((size_t)(b * S_ + row_base)) * HID_ + h * HD_;
#pragma unroll
        for (int j = 0; j < 4; j++) {
            int k0 = j * 16 + 2 * t;
            aq[j][0] = *(const uint32_t*)&qb[(size_t)g * HID_ + k0];
            aq[j][1] = *(const uint32_t*)&qb[(size_t)(g + 8) * HID_ + k0];
            aq[j][2] = *(const uint32_t*)&qb[(size_t)g * HID_ + k0 + 8];
            aq[j][3] = *(const uint32_t*)&qb[(size_t)(g + 8) * HID_ + k0 + 8];
        }
    }

    float o[8][4];
#pragma unroll
    for (int i = 0; i < 8; i++)
#pragma unroll
        for (int j = 0; j < 4; j++) o[i][j] = 0.f;
    float m0 = -INFINITY, m1 = -INFINITY, l0 = 0.f, l1 = 0.f;

    const int ntiles = 2 * qt + 2;

    auto issue = [&](int kt, int st) {
        uint32_t so = sb + (uint32_t)st * 2 * KVT * 2;
#pragma unroll
        for (int i = 0; i < 2; i++) {
            int idx = tid + i * 256;
            int r = idx >> 3, q = idx & 7;
            size_t go = ((size_t)(b * S_ + kt * 64 + r)) * NKVD + kvh * HD_ + q * 8;
            uint32_t off = (r * LDK + q * 8) * 2;
            cp16(so + off,           k16 + go);
            cp16(so + KVT * 2 + off, v16 + go);
        }
        cp_commit();
    };

    issue(0, 0);
    if (ntiles > 1) issue(1, 1);

    for (int kt = 0; kt < ntiles; kt++) {
        if (kt + 1 < ntiles) cp_wait1(); else cp_wait0();
        __syncthreads();
        if (kt + 2 < ntiles) issue(kt + 2, (kt + 2) % FSTG);

        const uint32_t sg = sb + (uint32_t)(kt % FSTG) * 2 * KVT * 2;
        const uint32_t sK_ = sg;
        const uint32_t sV_ = sg + KVT * 2;

        const bool skip = (kt * 64) > (row_base + 15);
        if (!skip) {
            float s[8][4];
#pragma unroll
            for (int i = 0; i < 8; i++)
#pragma unroll
                for (int j = 0; j < 4; j++) s[i][j] = 0.f;
#pragma unroll
            for (int j = 0; j < 4; j++) {
                const int kb = j * 16 + kq * 8;
#pragma unroll
                for (int kp = 0; kp < 4; kp++) {
                    uint32_t ad = ((kp * 16 + l8 + half_ * 8) * LDK + kb) * 2;
                    uint32_t th[4];
                    ldsm4(th, sK_ + ad);
                    uint32_t be0[2] = {th[0], th[2]}, be1[2] = {th[1], th[3]};
                    mma_f16(s[2 * kp],     aq[j], be0);
                    mma_f16(s[2 * kp + 1], aq[j], be1);
                }
            }
            const int r0 = row_base + g, r1 = row_base + g + 8;
#pragma unroll
            for (int ni = 0; ni < 8; ni++) {
                int c0 = kt * 64 + ni * 8 + 2 * t;
                if ((kt * 64 + 63) > r0 || (kt * 64 + 63) > r1) {
                    if (c0 > r0)     s[ni][0] = -INFINITY;
                    if (c0 + 1 > r0) s[ni][1] = -INFINITY;
                    if (c0 > r1)     s[ni][2] = -INFINITY;
                    if (c0 + 1 > r1) s[ni][3] = -INFINITY;
                }
            }
            float mx0 = -INFINITY, mx1 = -INFINITY;
#pragma unroll
            for (int ni = 0; ni < 8; ni++) {
                mx0 = fmaxf(mx0, fmaxf(s[ni][0], s[ni][1]));
                mx1 = fmaxf(mx1, fmaxf(s[ni][2], s[ni][3]));
            }
            mx0 = fmaxf(mx0, __shfl_xor_sync(0xffffffff, mx0, 1));
            mx0 = fmaxf(mx0, __shfl_xor_sync(0xffffffff, mx0, 2));
            mx1 = fmaxf(mx1, __shfl_xor_sync(0xffffffff, mx1, 1));
            mx1 = fmaxf(mx1, __shfl_xor_sync(0xffffffff, mx1, 2));

            float mn0 = fmaxf(m0, mx0), mn1 = fmaxf(m1, mx1);
            float f0 = exp2f(m0 - mn0), f1 = exp2f(m1 - mn1);
            m0 = mn0; m1 = mn1;

            float sum0 = 0.f, sum1 = 0.f;
#pragma unroll
            for (int ni = 0; ni < 8; ni++) {
                s[ni][0] = exp2f(s[ni][0] - mn0);
                s[ni][1] = exp2f(s[ni][1] - mn0);
                s[ni][2] = exp2f(s[ni][2] - mn1);
                s[ni][3] = exp2f(s[ni][3] - mn1);
                sum0 += s[ni][0] + s[ni][1];
                sum1 += s[ni][2] + s[ni][3];
            }
            sum0 += __shfl_xor_sync(0xffffffff, sum0, 1);
            sum0 += __shfl_xor_sync(0xffffffff, sum0, 2);
            sum1 += __shfl_xor_sync(0xffffffff, sum1, 1);
            sum1 += __shfl_xor_sync(0xffffffff, sum1, 2);
            l0 = l0 * f0 + sum0;
            l1 = l1 * f1 + sum1;

#pragma unroll
            for (int nd = 0; nd < 8; nd++) {
                o[nd][0] *= f0; o[nd][1] *= f0;
                o[nd][2] *= f1; o[nd][3] *= f1;
            }

            uint32_t pf[4][4];
#pragma unroll
            for (int j = 0; j < 4; j++) {
                pf[j][0] = pack_f16(s[2 * j][0],     s[2 * j][1]);
                pf[j][1] = pack_f16(s[2 * j][2],     s[2 * j][3]);
                pf[j][2] = pack_f16(s[2 * j + 1][0], s[2 * j + 1][1]);
                pf[j][3] = pack_f16(s[2 * j + 1][2], s[2 * j + 1][3]);
            }

#pragma unroll
            for (int j = 0; j < 4; j++) {
#pragma unroll
                for (int dp = 0; dp < 4; dp++) {
                    uint32_t ad = ((j * 16 + kq * 8 + l8) * LDK + dp * 16 + half_ * 8) * 2;
                    uint32_t th[4];
                    ldsm4t(th, sV_ + ad);
                    uint32_t b0a[2] = {th[0], th[2]}, b1a[2] = {th[1], th[3]};
                    mma_f16(o[2 * dp],     pf[j], b0a);
                    mma_f16(o[2 * dp + 1], pf[j], b1a);
                }
            }
        }
    }

    float li0 = 1.0f / l0, li1 = 1.0f / l1;
    const size_t r0 = (size_t)(b * S_ + row_base + g) * HID_ + h * HD_;
    const size_t r1 = (size_t)(b * S_ + row_base + g + 8) * HID_ + h * HD_;
#pragma unroll
    for (int nd = 0; nd < 8; nd++) {
        int c = nd * 8 + 2 * t;
        *(uint32_t*)&c16[r0 + c] = pack_f16(o[nd][0] * li0, o[nd][1] * li0);
        *(uint32_t*)&c16[r1 + c] = pack_f16(o[nd][2] * li1, o[nd][3] * li1);
    }
}

// ---------------------------------------------------------------------------
// Launch
// ---------------------------------------------------------------------------
extern "C" void kernel_launch(void* const* d_in, const int* in_sizes, int n_in,
                              void* d_out, int out_size)
{
    const float* hidden = (const float*)d_in[0];
    const float* wq = (const float*)d_in[2];
    const float* wk = (const float*)d_in[3];
    const float* wv = (const float*)d_in[4];
    const float* wo = (const float*)d_in[5];
    float* out = (float*)d_out;

    __half *h16, *wc16, *wo16, *q16, *k16, *v16, *c16;
    cudaGetSymbolAddress((void**)&h16, g_h16);
    cudaGetSymbolAddress((void**)&wc16, g_wc16); cudaGetSymbolAddress((void**)&wo16, g_wo16);
    cudaGetSymbolAddress((void**)&q16, g_q16);   cudaGetSymbolAddress((void**)&k16, g_k16);
    cudaGetSymbolAddress((void**)&v16, g_v16);   cudaGetSymbolAddress((void**)&c16, g_c16);

    const int GEMM_DYN = GSTG * STG_EL * 2;      // 92160 B
    const int FLASH_DYN = FSTG * 2 * KVT * 2;    // 55296 B
    cudaFuncSetAttribute(gemm_mma, cudaFuncAttributeMaxDynamicSharedMemorySize, GEMM_DYN);
    cudaFuncSetAttribute(flash_mma, cudaFuncAttributeMaxDynamicSharedMemorySize, FLASH_DYN);

    // Fused converts (vectorized) + rope table
    conv_all<<<(CTOT / 4 + 255) / 256, 256>>>(hidden, wq, wk, wv, wo, h16, wc16, wo16);
    rope_table_kernel<<<(S_ * 32) / 256, 256>>>();

    // Fused QKV projection + RoPE epilogue (writes q16(log2-scaled)/k16/v16)
    gemm_mma<<<dim3(NQKV / BN, M_TOT / BM), 512, GEMM_DYN>>>(
        h16, wc16, out /*unused*/, q16, k16, v16, 1, M_TOT, NQKV, HID_);

    // Flash attention (fp16, exp2 softmax; 2 CTAs/SM; writes fp16 ctx)
    flash_mma<<<dim3(S_ / 128, NH_, B_), 256, FLASH_DYN>>>(q16, k16, v16, c16);

    // O projection (fp32 output)
    gemm_mma<<<dim3(HID_ / BN, M_TOT / BM), 512, GEMM_DYN>>>(
        c16, wo16, out, q16, k16, v16, 0, M_TOT, HID_, HID_);
}